// round 10
// baseline (speedup 1.0000x reference)
#include <cuda_runtime.h>
#include <cuda_bf16.h>

#define BB 4
#define CIN 64
#define CO 128
#define HH 256
#define WW 256
#define HWP 65536
#define NOUT (BB*4*HWP)   // 1048576

typedef unsigned long long u64;

// scratch
__device__ float g_h[(size_t)BB * CO * HWP];                          // conv1 out [b][cout][pix]
__device__ __align__(256) unsigned short g_xh[(size_t)BB * HWP * 64]; // x hi, [b][pix][ci] bf16
__device__ __align__(256) unsigned short g_xl[(size_t)BB * HWP * 64]; // x lo
__device__ __align__(256) unsigned char  g_wp[18 * 16384];            // 9 taps x {hi,lo}, swizzled [cout][ci]

// ---- f32x2 helpers --------------------------------------------------------
__device__ __forceinline__ void fma2(u64& d, u64 a, u64 b) {
    asm("fma.rn.f32x2 %0, %1, %2, %0;" : "+l"(d) : "l"(a), "l"(b));
}
__device__ __forceinline__ u64 dup2(float x) {
    u64 d; asm("mov.b64 %0, {%1, %1};" : "=l"(d) : "f"(x)); return d;
}
__device__ __forceinline__ float2 unpk(u64 d) {
    float2 r; asm("mov.b64 {%0, %1}, %2;" : "=f"(r.x), "=f"(r.y) : "l"(d));
    return r;
}

// ---- fast transcendentals (abs err ~1e-7) ---------------------------------
__device__ __forceinline__ float fast_tanh(float x) {
    float e;
    asm("ex2.approx.f32 %0, %1;" : "=f"(e) : "f"(x * 2.8853900817779268f));
    float r;
    asm("rcp.approx.f32 %0, %1;" : "=f"(r) : "f"(1.0f + e));
    return fmaf(-2.0f, r, 1.0f);
}
__device__ __forceinline__ float fast_sigmoid(float x) {
    float e;
    asm("ex2.approx.f32 %0, %1;" : "=f"(e) : "f"(-x * 1.4426950408889634f));
    float r;
    asm("rcp.approx.f32 %0, %1;" : "=f"(r) : "f"(1.0f + e));
    return r;
}

// ---- cp.async helpers -----------------------------------------------------
__device__ __forceinline__ void cpa16(unsigned saddr, const void* gaddr) {
    asm volatile("cp.async.cg.shared.global [%0], [%1], 16;"
                 :: "r"(saddr), "l"(gaddr));
}
__device__ __forceinline__ void cpa16z(unsigned saddr, const void* gaddr, int ok) {
    asm volatile("cp.async.cg.shared.global [%0], [%1], 16, %2;"
                 :: "r"(saddr), "l"(gaddr), "r"(ok ? 16 : 0));
}
__device__ __forceinline__ void cpa4z(unsigned saddr, const void* gaddr, int pred) {
    asm volatile("cp.async.ca.shared.global [%0], [%1], 4, %2;"
                 :: "r"(saddr), "l"(gaddr), "r"(pred ? 4 : 0));
}
__device__ __forceinline__ void cpa_commit() {
    asm volatile("cp.async.commit_group;");
}
__device__ __forceinline__ void cpa_wait_all() {
    asm volatile("cp.async.wait_group 0;");
}

// ---- legacy tensor core: ldmatrix + mma.sync ------------------------------
__device__ __forceinline__ void ldmx4(unsigned& r0, unsigned& r1,
                                      unsigned& r2, unsigned& r3, unsigned a) {
    asm volatile("ldmatrix.sync.aligned.m8n8.x4.shared.b16 {%0,%1,%2,%3}, [%4];"
                 : "=r"(r0), "=r"(r1), "=r"(r2), "=r"(r3) : "r"(a));
}
__device__ __forceinline__ void mma_bf16(float* d, unsigned a0, unsigned a1,
                                         unsigned a2, unsigned a3,
                                         unsigned b0, unsigned b1) {
    asm volatile(
        "mma.sync.aligned.m16n8k16.row.col.f32.bf16.bf16.f32 "
        "{%0,%1,%2,%3}, {%4,%5,%6,%7}, {%8,%9}, {%0,%1,%2,%3};"
        : "+f"(d[0]), "+f"(d[1]), "+f"(d[2]), "+f"(d[3])
        : "r"(a0), "r"(a1), "r"(a2), "r"(a3), "r"(b0), "r"(b1));
}
__device__ __forceinline__ int swz(int off) { return off ^ ((off >> 3) & 0x70); }

// ---------------------------------------------------------------------------
// Prep 1: split conv weights to bf16 hi/lo, SW128-swizzled [cout][ci] tiles.
// ---------------------------------------------------------------------------
__global__ void wprep(const float* __restrict__ Wc) {
    int i = blockIdx.x * 256 + threadIdx.x;   // < 73728
    int tap = i >> 13, rem = i & 8191, cout = rem >> 6, ci = rem & 63;
    float v = Wc[cout * 576 + ci * 9 + tap];
    __nv_bfloat16 h = __float2bfloat16(v);
    float hf = __bfloat162float(h);
    __nv_bfloat16 l = __float2bfloat16(v - hf);
    int sw = swz(cout * 128 + ci * 2);
    *(unsigned short*)(g_wp + (tap * 2 + 0) * 16384 + sw) =
        *reinterpret_cast<unsigned short*>(&h);
    *(unsigned short*)(g_wp + (tap * 2 + 1) * 16384 + sw) =
        *reinterpret_cast<unsigned short*>(&l);
}

// ---------------------------------------------------------------------------
// Prep 2: transpose x to pixel-major bf16 hi/lo: g_x{h,l}[b][pix][ci]
// ---------------------------------------------------------------------------
__global__ void xprep(const float* __restrict__ x) {
    __shared__ unsigned short shh[32 * 66], shl[32 * 66];
    const int bx = blockIdx.x;
    const int b = bx >> 11;
    const int px0 = (bx & 2047) * 32;
    const int tid = threadIdx.x;
    for (int i = tid; i < 2048; i += 256) {
        int ci = i >> 5, p = i & 31;
        float v = x[(((size_t)b * 64 + ci) << 16) + px0 + p];
        __nv_bfloat16 h = __float2bfloat16(v);
        float hf = __bfloat162float(h);
        __nv_bfloat16 l = __float2bfloat16(v - hf);
        shh[p * 66 + ci] = *reinterpret_cast<unsigned short*>(&h);
        shl[p * 66 + ci] = *reinterpret_cast<unsigned short*>(&l);
    }
    __syncthreads();
    for (int i = tid; i < 1024; i += 256) {
        int p = i >> 5, j = i & 31;
        unsigned vh = shh[p * 66 + 2 * j] | ((unsigned)shh[p * 66 + 2 * j + 1] << 16);
        unsigned vl = shl[p * 66 + 2 * j] | ((unsigned)shl[p * 66 + 2 * j + 1] << 16);
        size_t rb = ((size_t)b * HWP + px0 + p) * 32 + j;
        reinterpret_cast<unsigned*>(g_xh)[rb] = vh;
        reinterpret_cast<unsigned*>(g_xl)[rb] = vl;
    }
}

// ---------------------------------------------------------------------------
// Kernel 1: conv1 via mma.sync bf16 3-pass (unchanged from R8).
// ---------------------------------------------------------------------------
#define SB_BYTES 49920
#define CV_SMEM (2*SB_BYTES + 65536 + 1024)

__global__ __launch_bounds__(256, 1) void conv_hmma(const float* __restrict__ bc) {
    extern __shared__ unsigned char dsm[];
    const int tid = threadIdx.x;
    const int w = tid >> 5, lane = tid & 31;
    const int blk = blockIdx.x;
    const int xh = blk & 1, y = (blk >> 1) & 255, b = blk >> 9;
    const int x0 = xh * 128;

    unsigned raw = (unsigned)__cvta_generic_to_shared(dsm);
    unsigned base = (raw + 1023) & ~1023u;
    unsigned sBh = base, sBl = base + SB_BYTES, sA = base + 2 * SB_BYTES;

    for (int i = tid; i < 6240; i += 256) {
        int half = (i >= 3120);
        int idx = half ? i - 3120 : i;
        int r = idx >> 3, c = idx & 7;
        int ky = r / 130, p = r % 130;
        int gy = y + ky - 1, gx = x0 + p - 1;
        int ok = (gy >= 0 && gy < HH && gx >= 0 && gx < WW);
        const unsigned char* src =
            (half ? (const unsigned char*)g_xl : (const unsigned char*)g_xh)
            + ((size_t)(b * HWP + (ok ? gy * WW + gx : 0)) * 128) + c * 16;
        cpa16z((half ? sBl : sBh) + swz(r * 128 + c * 16), src, ok);
    }
    cpa_commit();

    auto prefA = [&](int t, int buf) {
        const unsigned char* src = g_wp + t * 32768;
        unsigned dst = sA + buf * 32768;
#pragma unroll
        for (int j = 0; j < 8; j++) {
            int off = (tid * 8 + j) * 16;
            cpa16(dst + off, src + off);
        }
        cpa_commit();
    };
    prefA(0, 0);

    const int arow = (16 * w + (lane & 7) + ((lane >> 3) & 1) * 8) * 128
                   + ((lane >> 4) & 1) * 16;
    const int pxl  = (lane & 7) + ((lane >> 4) & 1) * 8;
    const int kextB = ((lane >> 3) & 1) * 16;

    float d[16][4];
#pragma unroll
    for (int j = 0; j < 16; j++)
#pragma unroll
        for (int q = 0; q < 4; q++) d[j][q] = 0.f;

    for (int t = 0; t < 9; t++) {
        cpa_wait_all();
        __syncthreads();
        if (t < 8) prefA(t + 1, (t + 1) & 1);

        const int rowb = (t / 3) * 130 + (t % 3);
        unsigned Ahi = sA + (t & 1) * 32768;
#pragma unroll
        for (int pass = 0; pass < 3; pass++) {
            unsigned Abase = (pass == 2) ? (Ahi + 16384) : Ahi;
            unsigned Bbase = (pass == 1) ? sBl : sBh;
#pragma unroll
            for (int k = 0; k < 4; k++) {
                unsigned a0, a1, a2, a3;
                ldmx4(a0, a1, a2, a3, Abase + swz(arow + k * 32));
                const int bc0 = (rowb + pxl) * 128 + k * 32 + kextB;
#pragma unroll
                for (int jp = 0; jp < 8; jp++) {
                    unsigned b0, b1, b2, b3;
                    ldmx4(b0, b1, b2, b3, Bbase + swz(bc0 + jp * 2048));
                    mma_bf16(d[2 * jp],     a0, a1, a2, a3, b0, b1);
                    mma_bf16(d[2 * jp + 1], a0, a1, a2, a3, b2, b3);
                }
            }
        }
        __syncthreads();
    }

    const int g = lane >> 2, c2 = (lane & 3) * 2;
    const int cout0 = 16 * w + g;
    const float bias0 = bc[cout0], bias1 = bc[cout0 + 8];
    float* h0 = g_h + ((size_t)(b * CO + cout0) << 16) + y * WW + x0 + c2;
    float* h1 = h0 + ((size_t)8 << 16);
#pragma unroll
    for (int j = 0; j < 16; j++) {
        float2 v0 = make_float2(d[j][0] + bias0, d[j][1] + bias0);
        float2 v1 = make_float2(d[j][2] + bias1, d[j][3] + bias1);
        *reinterpret_cast<float2*>(h0 + j * 8) = v0;
        *reinterpret_cast<float2*>(h1 + j * 8) = v1;
    }
}

// ---------------------------------------------------------------------------
// Kernel 2: MC dropout, S/D sparsity, 2 threads per pixel (split channels).
// Block 256 = 128 px x 2 halves; hs[128c][128px]; shfl_xor(1) combines halves.
// ---------------------------------------------------------------------------
#define LPAD 40   // entries per (t, half) list

__global__ __launch_bounds__(256, 2) void mc_kernel(
    const float* __restrict__ lms, const float* __restrict__ Wo,
    const float* __restrict__ bo, const float* __restrict__ masks,
    float* __restrict__ out)
{
    __shared__ float hs[128 * 128];                 // 64 KB [c][px]
    __shared__ float4 sWo[130];                     // [c]; sWo[128] = 0 (dummy)
    __shared__ __align__(16) unsigned lists[16 * 2 * LPAD];
    __shared__ int cnt[32];

    const int tid = threadIdx.x;
    const int blk = blockIdx.x;                     // b*512 + y*2 + xh
    const int b = blk >> 9, y = (blk >> 1) & 255, x0 = (blk & 1) * 128;
    const int px = tid >> 1, half = tid & 1, base = half * 64;

    if (tid < 129) {
        float4 v = make_float4(0.f, 0.f, 0.f, 0.f);
        if (tid < 128) {
            v.x = Wo[tid]; v.y = Wo[128 + tid];
            v.z = Wo[256 + tid]; v.w = Wo[384 + tid];
        }
        sWo[tid] = v;
    }
    if (tid < 32) {
        int t = tid >> 1, hf = tid & 1;
        unsigned* lp = &lists[(t * 2 + hf) * LPAD];
        int n = 0;
        for (int c = hf * 64; c < hf * 64 + 64; c++)
            if (masks[t * 128 + c] == 0.f)
                lp[n++] = (unsigned)c | ((unsigned)c << 16);
        while (n & 3) lp[n++] = 128u;    // wIdx=128 (zero weight), hsRow=0
        cnt[tid] = n;
    }
    {   // hs fill: thread = (channel, half-row segment)
        int c = tid >> 1, seg = (tid & 1) * 64;
        unsigned dst = (unsigned)__cvta_generic_to_shared(&hs[c * 128 + seg]);
        const float* src = g_h + ((size_t)(b * CO + c) << 16) + y * WW + x0 + seg;
#pragma unroll
        for (int j = 0; j < 16; j++)
            cpa16(dst + j * 16, src + j * 4);
        cpa_commit();
    }
    cpa_wait_all();
    __syncthreads();

    // ---- S over own 64 channels ----
    u64 S01 = 0ull, S23 = 0ull;
#pragma unroll 8
    for (int cc = 0; cc < 64; cc++) {
        int c = base + cc;
        float hv = hs[c * 128 + px];
        ulonglong2 w = *reinterpret_cast<const ulonglong2*>(&sWo[c]);
        u64 hd = dup2(hv);
        fma2(S01, w.x, hd);
        fma2(S23, w.y, hd);
    }

    // ---- D[t] over own dropped channels (padded x4, packed entries) ----
    u64 D01[16], D23[16];
#pragma unroll
    for (int t = 0; t < 16; t++) { D01[t] = 0ull; D23[t] = 0ull; }
#pragma unroll
    for (int t = 0; t < 16; t++) {
        const int n = cnt[t * 2 + half];
        const uint4* lp = reinterpret_cast<const uint4*>(&lists[(t * 2 + half) * LPAD]);
        for (int i = 0; i < n; i += 4) {
            uint4 e = lp[i >> 2];
#pragma unroll
            for (int q = 0; q < 4; q++) {
                unsigned en = (q == 0) ? e.x : (q == 1) ? e.y : (q == 2) ? e.z : e.w;
                unsigned wi = en & 0xFFFFu, hr = en >> 16;
                float hv = hs[hr * 128 + px];
                ulonglong2 w = *reinterpret_cast<const ulonglong2*>(&sWo[wi]);
                u64 hd = dup2(hv);
                fma2(D01[t], w.x, hd);
                fma2(D23[t], w.y, hd);
            }
        }
    }

    // ---- combine halves (pair is lanes 2k,2k+1 of same warp) ----
    float2 s01 = unpk(S01), s23 = unpk(S23);
    float a[16][4];
#pragma unroll
    for (int t = 0; t < 16; t++) {
        float2 d01 = unpk(D01[t]);
        float2 d23 = unpk(D23[t]);
        a[t][0] = s01.x - d01.x; a[t][1] = s01.y - d01.y;
        a[t][2] = s23.x - d23.x; a[t][3] = s23.y - d23.y;
#pragma unroll
        for (int o = 0; o < 4; o++)
            a[t][o] += __shfl_xor_sync(0xFFFFFFFFu, a[t][o], 1);
    }

    // ---- epilogue: this thread handles 2 of the 4 outputs ----
    const int pix = y * WW + x0 + px;
#pragma unroll
    for (int oo = 0; oo < 2; oo++) {
        int o = half * 2 + oo;
        float bb = bo[o];
        float s[16];
        float sum = 0.f;
#pragma unroll
        for (int t = 0; t < 16; t++) {
            float v = fast_tanh(a[t][o] + bb);
            s[t] = v;
            sum += v;
        }
        float mn = sum * 0.0625f;
        float var = 0.f;
#pragma unroll
        for (int t = 0; t < 16; t++) {
            float dd = s[t] - mn;
            var += dd * dd;
        }
        var *= (1.f / 15.f);
        int oidx = (b * 4 + o) * HWP + pix;
        out[NOUT + oidx]     = var;              // EU
        out[2 * NOUT + oidx] = mn + lms[oidx];   // mean
    }
}

// ---------------------------------------------------------------------------
// Kernel 3: AU conv. 8-channel chunks (16 stages, half the barriers of R9).
// ---------------------------------------------------------------------------
#define AFILL_N 2720         // 8 ci * 10 rows * 34 cols
#define AFILL_SLOTS 11

__global__ __launch_bounds__(256, 2) void au_kernel(
    const float* __restrict__ Wa, const float* __restrict__ ba,
    float* __restrict__ out)
{
    __shared__ float sWa[128 * 9 * 4];
    __shared__ float sX[2][8 * 10 * 36];

    const int tid = threadIdx.x;
    for (int i = tid; i < 128 * 36; i += 256) {
        int ci = i / 36, rem = i % 36, k = rem >> 2, o = rem & 3;
        sWa[i] = Wa[(o * 128 + ci) * 9 + k];
    }

    const int b  = blockIdx.z;
    const int y0 = blockIdx.y * 8;
    const int x0 = blockIdx.x * 32;
    const int row = tid >> 5;
    const int col = tid & 31;

    int smoff[AFILL_SLOTS]; int goff[AFILL_SLOTS]; int gok[AFILL_SLOTS];
#pragma unroll
    for (int s = 0; s < AFILL_SLOTS; s++) {
        int i = tid + s * 256;
        smoff[s] = -1; goff[s] = 0; gok[s] = 0;
        if (i < AFILL_N) {
            int ci = i / 340, r = (i / 34) % 10, c = i % 34;
            int gy = y0 - 1 + r, gx = x0 - 1 + c;
            smoff[s] = (ci * 10 + r) * 36 + c;
            if (gy >= 0 && gy < HH && gx >= 0 && gx < WW) {
                gok[s] = 1;
                goff[s] = ((b * CO + ci) * HH + gy) * WW + gx;
            }
        }
    }

    unsigned sXb[2];
    sXb[0] = (unsigned)__cvta_generic_to_shared(&sX[0][0]);
    sXb[1] = (unsigned)__cvta_generic_to_shared(&sX[1][0]);

    auto prefetch = [&](int cc, int bf) {
        const float* hsrc = g_h + (size_t)cc * 8 * HWP;
#pragma unroll
        for (int s = 0; s < AFILL_SLOTS; s++) {
            if (smoff[s] >= 0)
                cpa4z(sXb[bf] + smoff[s] * 4, hsrc + goff[s], gok[s]);
        }
        cpa_commit();
    };

    u64 auA = 0ull, auB = 0ull;

    prefetch(0, 0);
    __syncthreads();

    for (int cc = 0; cc < 16; cc++) {
        const int bf = cc & 1;
        cpa_wait_all();
        __syncthreads();
        if (cc < 15) prefetch(cc + 1, bf ^ 1);

        const float* sXc = &sX[bf][0];
#pragma unroll
        for (int ci = 0; ci < 8; ci++) {
#pragma unroll
            for (int ky = 0; ky < 3; ky++) {
                const float* xr = &sXc[(ci * 10 + row + ky) * 36 + col];
                float v0 = xr[0], v1 = xr[1], v2 = xr[2];
                const ulonglong2* wk = reinterpret_cast<const ulonglong2*>(
                    &sWa[((cc * 8 + ci) * 9 + ky * 3) * 4]);
                ulonglong2 w0 = wk[0], w1 = wk[1], w2 = wk[2];
                u64 x0d = dup2(v0), x1d = dup2(v1), x2d = dup2(v2);
                fma2(auA, w0.x, x0d); fma2(auB, w0.y, x0d);
                fma2(auA, w1.x, x1d); fma2(auB, w1.y, x1d);
                fma2(auA, w2.x, x2d); fma2(auB, w2.y, x2d);
            }
        }
        __syncthreads();
    }

    const int pix = (y0 + row) * WW + x0 + col;
    float2 f01 = unpk(auA);
    float2 f23 = unpk(auB);
    float av[4] = { f01.x, f01.y, f23.x, f23.y };
#pragma unroll
    for (int o = 0; o < 4; o++)
        out[(b * 4 + o) * HWP + pix] = fast_sigmoid(av[o] + ba[o]);
}

// ---------------------------------------------------------------------------
extern "C" void kernel_launch(void* const* d_in, const int* in_sizes, int n_in,
                              void* d_out, int out_size) {
    const float* x     = (const float*)d_in[0];
    const float* lms   = (const float*)d_in[1];
    const float* Wc    = (const float*)d_in[2];
    const float* bc    = (const float*)d_in[3];
    const float* Wo    = (const float*)d_in[4];
    const float* bo    = (const float*)d_in[5];
    const float* Wa    = (const float*)d_in[6];
    const float* ba    = (const float*)d_in[7];
    const float* masks = (const float*)d_in[8];
    float* out = (float*)d_out;

    cudaFuncSetAttribute(conv_hmma,
                         cudaFuncAttributeMaxDynamicSharedMemorySize, CV_SMEM);

    wprep<<<288, 256>>>(Wc);
    xprep<<<8192, 256>>>(x);
    conv_hmma<<<2048, 256, CV_SMEM>>>(bc);
    mc_kernel<<<2048, 256>>>(lms, Wo, bo, masks, out);
    au_kernel<<<dim3(8, 32, 4), 256>>>(Wa, ba, out);
}

// round 11
// speedup vs baseline: 1.1896x; 1.1896x over previous
#include <cuda_runtime.h>
#include <cuda_fp16.h>

#define BB 4
#define CIN 64
#define CO 128
#define HH 256
#define WW 256
#define HWP 65536
#define NOUT (BB*4*HWP)   // 1048576

typedef unsigned long long u64;

// scratch
__device__ float g_h[(size_t)BB * CO * HWP];                          // conv1 out [b][cout][pix]
__device__ __align__(256) unsigned short g_xh[(size_t)BB * HWP * 64]; // x fp16, [b][pix][ci]
__device__ __align__(256) unsigned char  g_wp[18 * 16384];            // 9 taps x {Wh,Wl} fp16, swizzled [cout][ci]

// ---- f32x2 helpers --------------------------------------------------------
__device__ __forceinline__ void fma2(u64& d, u64 a, u64 b) {
    asm("fma.rn.f32x2 %0, %1, %2, %0;" : "+l"(d) : "l"(a), "l"(b));
}
__device__ __forceinline__ u64 dup2(float x) {
    u64 d; asm("mov.b64 %0, {%1, %1};" : "=l"(d) : "f"(x)); return d;
}
__device__ __forceinline__ float2 unpk(u64 d) {
    float2 r; asm("mov.b64 {%0, %1}, %2;" : "=f"(r.x), "=f"(r.y) : "l"(d));
    return r;
}

// ---- fast transcendentals (abs err ~1e-7) ---------------------------------
__device__ __forceinline__ float fast_tanh(float x) {
    float e;
    asm("ex2.approx.f32 %0, %1;" : "=f"(e) : "f"(x * 2.8853900817779268f));
    float r;
    asm("rcp.approx.f32 %0, %1;" : "=f"(r) : "f"(1.0f + e));
    return fmaf(-2.0f, r, 1.0f);
}
__device__ __forceinline__ float fast_sigmoid(float x) {
    float e;
    asm("ex2.approx.f32 %0, %1;" : "=f"(e) : "f"(-x * 1.4426950408889634f));
    float r;
    asm("rcp.approx.f32 %0, %1;" : "=f"(r) : "f"(1.0f + e));
    return r;
}

// ---- cp.async helpers -----------------------------------------------------
__device__ __forceinline__ void cpa16(unsigned saddr, const void* gaddr) {
    asm volatile("cp.async.cg.shared.global [%0], [%1], 16;"
                 :: "r"(saddr), "l"(gaddr));
}
__device__ __forceinline__ void cpa16z(unsigned saddr, const void* gaddr, int ok) {
    asm volatile("cp.async.cg.shared.global [%0], [%1], 16, %2;"
                 :: "r"(saddr), "l"(gaddr), "r"(ok ? 16 : 0));
}
__device__ __forceinline__ void cpa4z(unsigned saddr, const void* gaddr, int pred) {
    asm volatile("cp.async.ca.shared.global [%0], [%1], 4, %2;"
                 :: "r"(saddr), "l"(gaddr), "r"(pred ? 4 : 0));
}
__device__ __forceinline__ void cpa_commit() {
    asm volatile("cp.async.commit_group;");
}
__device__ __forceinline__ void cpa_wait_all() {
    asm volatile("cp.async.wait_group 0;");
}

// ---- legacy tensor core: ldmatrix + mma.sync (fp16, fp32 accum) -----------
__device__ __forceinline__ void ldmx4(unsigned& r0, unsigned& r1,
                                      unsigned& r2, unsigned& r3, unsigned a) {
    asm volatile("ldmatrix.sync.aligned.m8n8.x4.shared.b16 {%0,%1,%2,%3}, [%4];"
                 : "=r"(r0), "=r"(r1), "=r"(r2), "=r"(r3) : "r"(a));
}
__device__ __forceinline__ void mma_f16(float* d, unsigned a0, unsigned a1,
                                        unsigned a2, unsigned a3,
                                        unsigned b0, unsigned b1) {
    asm volatile(
        "mma.sync.aligned.m16n8k16.row.col.f32.f16.f16.f32 "
        "{%0,%1,%2,%3}, {%4,%5,%6,%7}, {%8,%9}, {%0,%1,%2,%3};"
        : "+f"(d[0]), "+f"(d[1]), "+f"(d[2]), "+f"(d[3])
        : "r"(a0), "r"(a1), "r"(a2), "r"(a3), "r"(b0), "r"(b1));
}
__device__ __forceinline__ int swz(int off) { return off ^ ((off >> 3) & 0x70); }

// ---------------------------------------------------------------------------
// Prep 1: split conv weights to fp16 Wh + Wl (22-bit capture), SW128-swizzled
// [cout][ci] tiles: tile tap*2 = hi, tap*2+1 = lo.
// ---------------------------------------------------------------------------
__global__ void wprep(const float* __restrict__ Wc) {
    int i = blockIdx.x * 256 + threadIdx.x;   // < 73728
    int tap = i >> 13, rem = i & 8191, cout = rem >> 6, ci = rem & 63;
    float v = Wc[cout * 576 + ci * 9 + tap];
    __half h = __float2half_rn(v);
    float hf = __half2float(h);
    __half l = __float2half_rn(v - hf);
    int sw = swz(cout * 128 + ci * 2);
    *(unsigned short*)(g_wp + (tap * 2 + 0) * 16384 + sw) =
        *reinterpret_cast<unsigned short*>(&h);
    *(unsigned short*)(g_wp + (tap * 2 + 1) * 16384 + sw) =
        *reinterpret_cast<unsigned short*>(&l);
}

// ---------------------------------------------------------------------------
// Prep 2: transpose x to pixel-major fp16: g_xh[b][pix][ci]
// ---------------------------------------------------------------------------
__global__ void xprep(const float* __restrict__ x) {
    __shared__ unsigned short shh[32 * 66];
    const int bx = blockIdx.x;
    const int b = bx >> 11;
    const int px0 = (bx & 2047) * 32;
    const int tid = threadIdx.x;
    for (int i = tid; i < 2048; i += 256) {
        int ci = i >> 5, p = i & 31;
        float v = x[(((size_t)b * 64 + ci) << 16) + px0 + p];
        __half h = __float2half_rn(v);
        shh[p * 66 + ci] = *reinterpret_cast<unsigned short*>(&h);
    }
    __syncthreads();
    for (int i = tid; i < 1024; i += 256) {
        int p = i >> 5, j = i & 31;
        unsigned vh = shh[p * 66 + 2 * j] | ((unsigned)shh[p * 66 + 2 * j + 1] << 16);
        size_t rb = ((size_t)b * HWP + px0 + p) * 32 + j;
        reinterpret_cast<unsigned*>(g_xh)[rb] = vh;
    }
}

// ---------------------------------------------------------------------------
// Kernel 1: conv1 via mma.sync fp16 2-pass: (Wh + Wl) * Xh.
// CTA = 128 cout x 128 px. B loaded once (3 ky-rows x 130 px); A streamed/tap.
// ---------------------------------------------------------------------------
#define SB_BYTES 49920          // 390 rows * 128 B (fp16, hi only)
#define CV_SMEM (SB_BYTES + 65536 + 1024)

__global__ __launch_bounds__(256, 1) void conv_hmma(const float* __restrict__ bc) {
    extern __shared__ unsigned char dsm[];
    const int tid = threadIdx.x;
    const int w = tid >> 5, lane = tid & 31;
    const int blk = blockIdx.x;
    const int xh = blk & 1, y = (blk >> 1) & 255, b = blk >> 9;
    const int x0 = xh * 128;

    unsigned raw = (unsigned)__cvta_generic_to_shared(dsm);
    unsigned base = (raw + 1023) & ~1023u;
    unsigned sBh = base, sA = base + SB_BYTES;

    // B fill (once): 3 ky-rows x 130 px x 128B, zfill at edges
    for (int i = tid; i < 3120; i += 256) {
        int r = i >> 3, c = i & 7;               // r < 390, c = 16B chunk
        int ky = r / 130, p = r % 130;
        int gy = y + ky - 1, gx = x0 + p - 1;
        int ok = (gy >= 0 && gy < HH && gx >= 0 && gx < WW);
        const unsigned char* src = (const unsigned char*)g_xh
            + ((size_t)(b * HWP + (ok ? gy * WW + gx : 0)) * 128) + c * 16;
        cpa16z(sBh + swz(r * 128 + c * 16), src, ok);
    }
    cpa_commit();

    auto prefA = [&](int t, int buf) {
        const unsigned char* src = g_wp + t * 32768;   // Wh 16K + Wl 16K
        unsigned dst = sA + buf * 32768;
#pragma unroll
        for (int j = 0; j < 8; j++) {
            int off = (tid * 8 + j) * 16;
            cpa16(dst + off, src + off);
        }
        cpa_commit();
    };
    prefA(0, 0);

    const int arow = (16 * w + (lane & 7) + ((lane >> 3) & 1) * 8) * 128
                   + ((lane >> 4) & 1) * 16;
    const int pxl  = (lane & 7) + ((lane >> 4) & 1) * 8;
    const int kextB = ((lane >> 3) & 1) * 16;

    float d[16][4];
#pragma unroll
    for (int j = 0; j < 16; j++)
#pragma unroll
        for (int q = 0; q < 4; q++) d[j][q] = 0.f;

    for (int t = 0; t < 9; t++) {
        cpa_wait_all();
        __syncthreads();
        if (t < 8) prefA(t + 1, (t + 1) & 1);

        const int rowb = (t / 3) * 130 + (t % 3);
        unsigned Abuf = sA + (t & 1) * 32768;
#pragma unroll
        for (int k = 0; k < 4; k++) {
            unsigned ah0, ah1, ah2, ah3, al0, al1, al2, al3;
            ldmx4(ah0, ah1, ah2, ah3, Abuf + swz(arow + k * 32));
            ldmx4(al0, al1, al2, al3, Abuf + 16384 + swz(arow + k * 32));
            const int bc0 = (rowb + pxl) * 128 + k * 32 + kextB;
#pragma unroll
            for (int jp = 0; jp < 8; jp++) {
                unsigned b0, b1, b2, b3;
                ldmx4(b0, b1, b2, b3, sBh + swz(bc0 + jp * 2048));
                mma_f16(d[2 * jp],     ah0, ah1, ah2, ah3, b0, b1);
                mma_f16(d[2 * jp],     al0, al1, al2, al3, b0, b1);
                mma_f16(d[2 * jp + 1], ah0, ah1, ah2, ah3, b2, b3);
                mma_f16(d[2 * jp + 1], al0, al1, al2, al3, b2, b3);
            }
        }
        __syncthreads();
    }

    const int g = lane >> 2, c2 = (lane & 3) * 2;
    const int cout0 = 16 * w + g;
    const float bias0 = bc[cout0], bias1 = bc[cout0 + 8];
    float* h0 = g_h + ((size_t)(b * CO + cout0) << 16) + y * WW + x0 + c2;
    float* h1 = h0 + ((size_t)8 << 16);
#pragma unroll
    for (int j = 0; j < 16; j++) {
        float2 v0 = make_float2(d[j][0] + bias0, d[j][1] + bias0);
        float2 v1 = make_float2(d[j][2] + bias1, d[j][3] + bias1);
        *reinterpret_cast<float2*>(h0 + j * 8) = v0;
        *reinterpret_cast<float2*>(h1 + j * 8) = v1;
    }
}

// ---------------------------------------------------------------------------
// Kernel 2 (FUSED mc + au): R8 version verbatim (best measured: 285 us).
// ---------------------------------------------------------------------------
#define FILL_N 1360          // 4 ci * 10 rows * 34 cols
#define FILL_SLOTS 6

__global__ __launch_bounds__(256, 2) void mcau_kernel(
    const float* __restrict__ lms, const float* __restrict__ Wo,
    const float* __restrict__ bo, const float* __restrict__ masks,
    const float* __restrict__ Wa, const float* __restrict__ ba,
    float* __restrict__ out)
{
    __shared__ float sWm[128 * 64];     // [c][t][o], o fastest (32 KB)
    __shared__ float sWa[128 * 9 * 4];  // (18 KB)
    __shared__ float sX[2][4 * 10 * 36]; // ping-pong h tile

    const int tid = threadIdx.x;
    for (int i = tid; i < 128 * 64; i += 256) {
        int c = i >> 6, t = (i >> 2) & 15, o = i & 3;
        sWm[i] = Wo[o * 128 + c] * masks[t * 128 + c];
    }
    for (int i = tid; i < 128 * 36; i += 256) {
        int ci = i / 36, rem = i % 36, k = rem >> 2, o = rem & 3;
        sWa[i] = Wa[(o * 128 + ci) * 9 + k];
    }

    const int b  = blockIdx.z;
    const int y0 = blockIdx.y * 8;
    const int x0 = blockIdx.x * 32;
    const int row = tid >> 5;
    const int col = tid & 31;

    int smoff[FILL_SLOTS]; int goff[FILL_SLOTS]; int gok[FILL_SLOTS];
#pragma unroll
    for (int s = 0; s < FILL_SLOTS; s++) {
        int i = tid + s * 256;
        smoff[s] = -1; goff[s] = 0; gok[s] = 0;
        if (i < FILL_N) {
            int ci = i / 340, r = (i / 34) % 10, c = i % 34;
            int gy = y0 - 1 + r, gx = x0 - 1 + c;
            smoff[s] = (ci * 10 + r) * 36 + c;
            if (gy >= 0 && gy < HH && gx >= 0 && gx < WW) {
                gok[s] = 1;
                goff[s] = ((b * CO + ci) * HH + gy) * WW + gx;
            }
        }
    }

    unsigned sXb[2];
    sXb[0] = (unsigned)__cvta_generic_to_shared(&sX[0][0]);
    sXb[1] = (unsigned)__cvta_generic_to_shared(&sX[1][0]);

    auto prefetch = [&](int cc, int bf) {
        const float* hsrc = g_h + (size_t)cc * 4 * HWP;
#pragma unroll
        for (int s = 0; s < FILL_SLOTS; s++) {
            if (smoff[s] >= 0)
                cpa4z(sXb[bf] + smoff[s] * 4, hsrc + goff[s], gok[s]);
        }
        cpa_commit();
    };

    u64 mcA[16], mcB[16];
#pragma unroll
    for (int t = 0; t < 16; t++) { mcA[t] = 0ull; mcB[t] = 0ull; }
    u64 auA = 0ull, auB = 0ull;

    prefetch(0, 0);
    __syncthreads();

    for (int cc = 0; cc < 32; cc++) {
        const int bf = cc & 1;
        cpa_wait_all();
        __syncthreads();
        if (cc < 31) prefetch(cc + 1, bf ^ 1);

        const float* sXc = &sX[bf][0];
#pragma unroll
        for (int ci = 0; ci < 4; ci++) {
            float hv = sXc[(ci * 10 + row + 1) * 36 + col + 1];
            u64 hd = dup2(hv);
            const ulonglong2* wr =
                reinterpret_cast<const ulonglong2*>(&sWm[(cc * 4 + ci) * 64]);
#pragma unroll
            for (int t = 0; t < 16; t++) {
                ulonglong2 w = wr[t];
                fma2(mcA[t], w.x, hd);
                fma2(mcB[t], w.y, hd);
            }
#pragma unroll
            for (int ky = 0; ky < 3; ky++) {
                const float* xr = &sXc[(ci * 10 + row + ky) * 36 + col];
                float v0 = xr[0], v1 = xr[1], v2 = xr[2];
                const ulonglong2* wk = reinterpret_cast<const ulonglong2*>(
                    &sWa[((cc * 4 + ci) * 9 + ky * 3) * 4]);
                ulonglong2 w0 = wk[0], w1 = wk[1], w2 = wk[2];
                u64 x0d = dup2(v0), x1d = dup2(v1), x2d = dup2(v2);
                fma2(auA, w0.x, x0d); fma2(auB, w0.y, x0d);
                fma2(auA, w1.x, x1d); fma2(auB, w1.y, x1d);
                fma2(auA, w2.x, x2d); fma2(auB, w2.y, x2d);
            }
        }
        __syncthreads();
    }

    const int pix  = (y0 + row) * WW + x0 + col;

    float a[16][4];
#pragma unroll
    for (int t = 0; t < 16; t++) {
        float2 f01 = unpk(mcA[t]);
        float2 f23 = unpk(mcB[t]);
        a[t][0] = f01.x; a[t][1] = f01.y; a[t][2] = f23.x; a[t][3] = f23.y;
    }
#pragma unroll
    for (int o = 0; o < 4; o++) {
        float bb = bo[o];
        float s[16];
        float sum = 0.f;
#pragma unroll
        for (int t = 0; t < 16; t++) {
            float v = fast_tanh(a[t][o] + bb);
            s[t] = v;
            sum += v;
        }
        float mn = sum * 0.0625f;
        float var = 0.f;
#pragma unroll
        for (int t = 0; t < 16; t++) {
            float dd = s[t] - mn;
            var += dd * dd;
        }
        var *= (1.f / 15.f);
        int oidx = (b * 4 + o) * HWP + pix;
        out[NOUT + oidx]     = var;              // EU
        out[2 * NOUT + oidx] = mn + lms[oidx];   // mean
    }

    {
        float2 f01 = unpk(auA);
        float2 f23 = unpk(auB);
        float av[4] = { f01.x, f01.y, f23.x, f23.y };
#pragma unroll
        for (int o = 0; o < 4; o++)
            out[(b * 4 + o) * HWP + pix] = fast_sigmoid(av[o] + ba[o]);  // AU
    }
}

// ---------------------------------------------------------------------------
extern "C" void kernel_launch(void* const* d_in, const int* in_sizes, int n_in,
                              void* d_out, int out_size) {
    const float* x     = (const float*)d_in[0];
    const float* lms   = (const float*)d_in[1];
    const float* Wc    = (const float*)d_in[2];
    const float* bc    = (const float*)d_in[3];
    const float* Wo    = (const float*)d_in[4];
    const float* bo    = (const float*)d_in[5];
    const float* Wa    = (const float*)d_in[6];
    const float* ba    = (const float*)d_in[7];
    const float* masks = (const float*)d_in[8];
    float* out = (float*)d_out;

    cudaFuncSetAttribute(conv_hmma,
                         cudaFuncAttributeMaxDynamicSharedMemorySize, CV_SMEM);

    wprep<<<288, 256>>>(Wc);
    xprep<<<8192, 256>>>(x);
    conv_hmma<<<2048, 256, CV_SMEM>>>(bc);
    mcau_kernel<<<dim3(8, 32, 4), 256>>>(lms, Wo, bo, masks, Wa, ba, out);
}

// round 12
// speedup vs baseline: 1.6399x; 1.3785x over previous
#include <cuda_runtime.h>
#include <cuda_fp16.h>

#define BB 4
#define CIN 64
#define CO 128
#define HH 256
#define WW 256
#define HWP 65536
#define NOUT (BB*4*HWP)   // 1048576

typedef unsigned long long u64;

// scratch
__device__ float g_h[(size_t)BB * CO * HWP];                          // conv1 out [b][cout][pix]
__device__ __align__(256) unsigned short g_xh[(size_t)BB * HWP * 64]; // x fp16, [b][pix][ci]
__device__ __align__(256) unsigned char  g_wp[9 * 16384];             // 9 taps fp16, swizzled [cout][ci]

// ---- f32x2 helpers --------------------------------------------------------
__device__ __forceinline__ void fma2(u64& d, u64 a, u64 b) {
    asm("fma.rn.f32x2 %0, %1, %2, %0;" : "+l"(d) : "l"(a), "l"(b));
}
__device__ __forceinline__ u64 dup2(float x) {
    u64 d; asm("mov.b64 %0, {%1, %1};" : "=l"(d) : "f"(x)); return d;
}
__device__ __forceinline__ float2 unpk(u64 d) {
    float2 r; asm("mov.b64 {%0, %1}, %2;" : "=f"(r.x), "=f"(r.y) : "l"(d));
    return r;
}

// ---- fast transcendentals --------------------------------------------------
__device__ __forceinline__ float fast_ex2(float x) {
    float e; asm("ex2.approx.f32 %0, %1;" : "=f"(e) : "f"(x)); return e;
}
__device__ __forceinline__ float fast_rcp(float x) {
    float r; asm("rcp.approx.f32 %0, %1;" : "=f"(r) : "f"(x)); return r;
}
__device__ __forceinline__ float fast_sigmoid(float x) {
    float e = fast_ex2(-x * 1.4426950408889634f);
    return fast_rcp(1.0f + e);
}

// ---- cp.async helpers -----------------------------------------------------
__device__ __forceinline__ void cpa16(unsigned saddr, const void* gaddr) {
    asm volatile("cp.async.cg.shared.global [%0], [%1], 16;"
                 :: "r"(saddr), "l"(gaddr));
}
__device__ __forceinline__ void cpa16z(unsigned saddr, const void* gaddr, int ok) {
    asm volatile("cp.async.cg.shared.global [%0], [%1], 16, %2;"
                 :: "r"(saddr), "l"(gaddr), "r"(ok ? 16 : 0));
}
__device__ __forceinline__ void cpa4z(unsigned saddr, const void* gaddr, int pred) {
    asm volatile("cp.async.ca.shared.global [%0], [%1], 4, %2;"
                 :: "r"(saddr), "l"(gaddr), "r"(pred ? 4 : 0));
}
__device__ __forceinline__ void cpa_commit() {
    asm volatile("cp.async.commit_group;");
}
__device__ __forceinline__ void cpa_wait_all() {
    asm volatile("cp.async.wait_group 0;");
}

// ---- legacy tensor core: ldmatrix + mma.sync (fp16, fp32 accum) -----------
__device__ __forceinline__ void ldmx4(unsigned& r0, unsigned& r1,
                                      unsigned& r2, unsigned& r3, unsigned a) {
    asm volatile("ldmatrix.sync.aligned.m8n8.x4.shared.b16 {%0,%1,%2,%3}, [%4];"
                 : "=r"(r0), "=r"(r1), "=r"(r2), "=r"(r3) : "r"(a));
}
__device__ __forceinline__ void mma_f16(float* d, unsigned a0, unsigned a1,
                                        unsigned a2, unsigned a3,
                                        unsigned b0, unsigned b1) {
    asm volatile(
        "mma.sync.aligned.m16n8k16.row.col.f32.f16.f16.f32 "
        "{%0,%1,%2,%3}, {%4,%5,%6,%7}, {%8,%9}, {%0,%1,%2,%3};"
        : "+f"(d[0]), "+f"(d[1]), "+f"(d[2]), "+f"(d[3])
        : "r"(a0), "r"(a1), "r"(a2), "r"(a3), "r"(b0), "r"(b1));
}
__device__ __forceinline__ int swz(int off) { return off ^ ((off >> 3) & 0x70); }

// ---------------------------------------------------------------------------
// Prep 1: conv weights -> fp16 (single), SW128-swizzled [cout][ci] tiles.
// ---------------------------------------------------------------------------
__global__ void wprep(const float* __restrict__ Wc) {
    int i = blockIdx.x * 256 + threadIdx.x;   // < 73728
    int tap = i >> 13, rem = i & 8191, cout = rem >> 6, ci = rem & 63;
    float v = Wc[cout * 576 + ci * 9 + tap];
    __half h = __float2half_rn(v);
    int sw = swz(cout * 128 + ci * 2);
    *(unsigned short*)(g_wp + tap * 16384 + sw) =
        *reinterpret_cast<unsigned short*>(&h);
}

// ---------------------------------------------------------------------------
// Prep 2: transpose x to pixel-major fp16: g_xh[b][pix][ci]
// ---------------------------------------------------------------------------
__global__ void xprep(const float* __restrict__ x) {
    __shared__ unsigned short shh[32 * 66];
    const int bx = blockIdx.x;
    const int b = bx >> 11;
    const int px0 = (bx & 2047) * 32;
    const int tid = threadIdx.x;
    for (int i = tid; i < 2048; i += 256) {
        int ci = i >> 5, p = i & 31;
        float v = x[(((size_t)b * 64 + ci) << 16) + px0 + p];
        __half h = __float2half_rn(v);
        shh[p * 66 + ci] = *reinterpret_cast<unsigned short*>(&h);
    }
    __syncthreads();
    for (int i = tid; i < 1024; i += 256) {
        int p = i >> 5, j = i & 31;
        unsigned vh = shh[p * 66 + 2 * j] | ((unsigned)shh[p * 66 + 2 * j + 1] << 16);
        size_t rb = ((size_t)b * HWP + px0 + p) * 32 + j;
        reinterpret_cast<unsigned*>(g_xh)[rb] = vh;
    }
}

// ---------------------------------------------------------------------------
// Kernel 1: conv1 via mma.sync fp16 SINGLE-pass. CTA = 128 cout x 128 px.
// ---------------------------------------------------------------------------
#define SB_BYTES 49920          // 390 rows * 128 B
#define CV_SMEM (SB_BYTES + 32768 + 1024)

__global__ __launch_bounds__(256, 2) void conv_hmma(const float* __restrict__ bc) {
    extern __shared__ unsigned char dsm[];
    const int tid = threadIdx.x;
    const int w = tid >> 5, lane = tid & 31;
    const int blk = blockIdx.x;
    const int xh = blk & 1, y = (blk >> 1) & 255, b = blk >> 9;
    const int x0 = xh * 128;

    unsigned raw = (unsigned)__cvta_generic_to_shared(dsm);
    unsigned base = (raw + 1023) & ~1023u;
    unsigned sBh = base, sA = base + SB_BYTES;

    // B fill (once): 3 ky-rows x 130 px x 128B, zfill at edges
    for (int i = tid; i < 3120; i += 256) {
        int r = i >> 3, c = i & 7;
        int ky = r / 130, p = r % 130;
        int gy = y + ky - 1, gx = x0 + p - 1;
        int ok = (gy >= 0 && gy < HH && gx >= 0 && gx < WW);
        const unsigned char* src = (const unsigned char*)g_xh
            + ((size_t)(b * HWP + (ok ? gy * WW + gx : 0)) * 128) + c * 16;
        cpa16z(sBh + swz(r * 128 + c * 16), src, ok);
    }
    cpa_commit();

    auto prefA = [&](int t, int buf) {
        const unsigned char* src = g_wp + t * 16384;
        unsigned dst = sA + buf * 16384;
#pragma unroll
        for (int j = 0; j < 4; j++) {
            int off = (tid * 4 + j) * 16;
            cpa16(dst + off, src + off);
        }
        cpa_commit();
    };
    prefA(0, 0);

    const int arow = (16 * w + (lane & 7) + ((lane >> 3) & 1) * 8) * 128
                   + ((lane >> 4) & 1) * 16;
    const int pxl  = (lane & 7) + ((lane >> 4) & 1) * 8;
    const int kextB = ((lane >> 3) & 1) * 16;

    float d[16][4];
#pragma unroll
    for (int j = 0; j < 16; j++)
#pragma unroll
        for (int q = 0; q < 4; q++) d[j][q] = 0.f;

    for (int t = 0; t < 9; t++) {
        cpa_wait_all();
        __syncthreads();
        if (t < 8) prefA(t + 1, (t + 1) & 1);

        const int rowb = (t / 3) * 130 + (t % 3);
        unsigned Abuf = sA + (t & 1) * 16384;
#pragma unroll
        for (int k = 0; k < 4; k++) {
            unsigned a0, a1, a2, a3;
            ldmx4(a0, a1, a2, a3, Abuf + swz(arow + k * 32));
            const int bc0 = (rowb + pxl) * 128 + k * 32 + kextB;
#pragma unroll
            for (int jp = 0; jp < 8; jp++) {
                unsigned b0, b1, b2, b3;
                ldmx4(b0, b1, b2, b3, sBh + swz(bc0 + jp * 2048));
                mma_f16(d[2 * jp],     a0, a1, a2, a3, b0, b1);
                mma_f16(d[2 * jp + 1], a0, a1, a2, a3, b2, b3);
            }
        }
        __syncthreads();
    }

    const int g = lane >> 2, c2 = (lane & 3) * 2;
    const int cout0 = 16 * w + g;
    const float bias0 = bc[cout0], bias1 = bc[cout0 + 8];
    float* h0 = g_h + ((size_t)(b * CO + cout0) << 16) + y * WW + x0 + c2;
    float* h1 = h0 + ((size_t)8 << 16);
#pragma unroll
    for (int j = 0; j < 16; j++) {
        float2 v0 = make_float2(d[j][0] + bias0, d[j][1] + bias0);
        float2 v1 = make_float2(d[j][2] + bias1, d[j][3] + bias1);
        *reinterpret_cast<float2*>(h0 + j * 8) = v0;
        *reinterpret_cast<float2*>(h1 + j * 8) = v1;
    }
}

// ---------------------------------------------------------------------------
// Kernel 2 (FUSED mc + au): t-split pixel pairs + batched-reciprocal tanh.
// Pair (2k,2k+1): each thread does t-half [half*8, half*8+8) for BOTH pixels
// (colE, colE+1); partials merged via shfl_xor(1). au: own pixel, unchanged.
// ---------------------------------------------------------------------------
#define FILL_N 1360          // 4 ci * 10 rows * 34 cols
#define FILL_SLOTS 6

__global__ __launch_bounds__(256, 2) void mcau_kernel(
    const float* __restrict__ lms, const float* __restrict__ Wo,
    const float* __restrict__ bo, const float* __restrict__ masks,
    const float* __restrict__ Wa, const float* __restrict__ ba,
    float* __restrict__ out)
{
    __shared__ float sWm[128 * 64];     // [c][t][o], o fastest (32 KB)
    __shared__ float sWa[128 * 9 * 4];  // (18 KB)
    __shared__ float sX[2][4 * 10 * 36]; // ping-pong h tile

    const int tid = threadIdx.x;
    for (int i = tid; i < 128 * 64; i += 256) {
        int c = i >> 6, t = (i >> 2) & 15, o = i & 3;
        sWm[i] = Wo[o * 128 + c] * masks[t * 128 + c];
    }
    for (int i = tid; i < 128 * 36; i += 256) {
        int ci = i / 36, rem = i % 36, k = rem >> 2, o = rem & 3;
        sWa[i] = Wa[(o * 128 + ci) * 9 + k];
    }

    const int b  = blockIdx.z;
    const int y0 = blockIdx.y * 8;
    const int x0 = blockIdx.x * 32;
    const int row  = tid >> 5;
    const int col  = tid & 31;
    const int half = tid & 1;         // t-half
    const int colE = col & ~1;        // pair pixel base

    int smoff[FILL_SLOTS]; int goff[FILL_SLOTS]; int gok[FILL_SLOTS];
#pragma unroll
    for (int s = 0; s < FILL_SLOTS; s++) {
        int i = tid + s * 256;
        smoff[s] = -1; goff[s] = 0; gok[s] = 0;
        if (i < FILL_N) {
            int ci = i / 340, r = (i / 34) % 10, c = i % 34;
            int gy = y0 - 1 + r, gx = x0 - 1 + c;
            smoff[s] = (ci * 10 + r) * 36 + c;
            if (gy >= 0 && gy < HH && gx >= 0 && gx < WW) {
                gok[s] = 1;
                goff[s] = ((b * CO + ci) * HH + gy) * WW + gx;
            }
        }
    }

    unsigned sXb[2];
    sXb[0] = (unsigned)__cvta_generic_to_shared(&sX[0][0]);
    sXb[1] = (unsigned)__cvta_generic_to_shared(&sX[1][0]);

    auto prefetch = [&](int cc, int bf) {
        const float* hsrc = g_h + (size_t)cc * 4 * HWP;
#pragma unroll
        for (int s = 0; s < FILL_SLOTS; s++) {
            if (smoff[s] >= 0)
                cpa4z(sXb[bf] + smoff[s] * 4, hsrc + goff[s], gok[s]);
        }
        cpa_commit();
    };

    u64 mA[8][2], mB[8][2];           // [tloc][px]: o01 / o23
#pragma unroll
    for (int t = 0; t < 8; t++) {
        mA[t][0] = 0ull; mA[t][1] = 0ull;
        mB[t][0] = 0ull; mB[t][1] = 0ull;
    }
    u64 auA = 0ull, auB = 0ull;

    prefetch(0, 0);
    __syncthreads();

    for (int cc = 0; cc < 32; cc++) {
        const int bf = cc & 1;
        cpa_wait_all();
        __syncthreads();
        if (cc < 31) prefetch(cc + 1, bf ^ 1);

        const float* sXc = &sX[bf][0];
#pragma unroll
        for (int ci = 0; ci < 4; ci++) {
            // --- mc: two pixels, own t-half ---
            const float* hr = &sXc[(ci * 10 + row + 1) * 36 + colE + 1];
            u64 h0 = dup2(hr[0]);
            u64 h1 = dup2(hr[1]);
            const ulonglong2* wr = reinterpret_cast<const ulonglong2*>(
                &sWm[(cc * 4 + ci) * 64 + half * 32]);
#pragma unroll
            for (int t = 0; t < 8; t++) {
                ulonglong2 wv = wr[t];
                fma2(mA[t][0], wv.x, h0); fma2(mA[t][1], wv.x, h1);
                fma2(mB[t][0], wv.y, h0); fma2(mB[t][1], wv.y, h1);
            }
            // --- au: 3x3 neighborhood, own pixel ---
#pragma unroll
            for (int ky = 0; ky < 3; ky++) {
                const float* xr = &sXc[(ci * 10 + row + ky) * 36 + col];
                float v0 = xr[0], v1 = xr[1], v2 = xr[2];
                const ulonglong2* wk = reinterpret_cast<const ulonglong2*>(
                    &sWa[((cc * 4 + ci) * 9 + ky * 3) * 4]);
                ulonglong2 w0 = wk[0], w1 = wk[1], w2 = wk[2];
                u64 x0d = dup2(v0), x1d = dup2(v1), x2d = dup2(v2);
                fma2(auA, w0.x, x0d); fma2(auB, w0.y, x0d);
                fma2(auA, w1.x, x1d); fma2(auB, w1.y, x1d);
                fma2(auA, w2.x, x2d); fma2(auB, w2.y, x2d);
            }
        }
        __syncthreads();
    }

    // ---- mc epilogue: tanh via batched reciprocal (1 rcp per 8) ----
    const float bo0 = bo[0], bo1 = bo[1], bo2 = bo[2], bo3 = bo[3];
    float sumS[2][4], sumQ[2][4];
#pragma unroll
    for (int p = 0; p < 2; p++)
#pragma unroll
        for (int o = 0; o < 4; o++) { sumS[p][o] = 0.f; sumQ[p][o] = 0.f; }

#pragma unroll
    for (int tl = 0; tl < 8; tl++) {
        float2 a0 = unpk(mA[tl][0]), b0v = unpk(mB[tl][0]);
        float2 a1 = unpk(mA[tl][1]), b1v = unpk(mB[tl][1]);
        float v[8];
        v[0] = a0.x + bo0;  v[1] = a0.y + bo1;
        v[2] = b0v.x + bo2; v[3] = b0v.y + bo3;
        v[4] = a1.x + bo0;  v[5] = a1.y + bo1;
        v[6] = b1v.x + bo2; v[7] = b1v.y + bo3;
        float dd[8];
#pragma unroll
        for (int i = 0; i < 8; i++) {
            float xc = fminf(v[i], 4.8f);             // cap: group product < 3e33
            dd[i] = 1.0f + fast_ex2(xc * 2.8853900817779268f);
        }
        float p01 = dd[0] * dd[1], p23 = dd[2] * dd[3];
        float p45 = dd[4] * dd[5], p67 = dd[6] * dd[7];
        float p0123 = p01 * p23, p4567 = p45 * p67;
        float r = fast_rcp(p0123 * p4567);
        float r0123 = r * p4567, r4567 = r * p0123;
        float i01 = r0123 * p23, i23 = r0123 * p01;
        float i45 = r4567 * p67, i67 = r4567 * p45;
        float inv[8];
        inv[0] = i01 * dd[1]; inv[1] = i01 * dd[0];
        inv[2] = i23 * dd[3]; inv[3] = i23 * dd[2];
        inv[4] = i45 * dd[5]; inv[5] = i45 * dd[4];
        inv[6] = i67 * dd[7]; inv[7] = i67 * dd[6];
#pragma unroll
        for (int i = 0; i < 8; i++) {
            float s = fmaf(-2.f, inv[i], 1.f);        // tanh
            int p = i >> 2, o = i & 3;
            sumS[p][o] += s;
            sumQ[p][o] = fmaf(s, s, sumQ[p][o]);
        }
    }

    // combine halves: send partial for PARTNER's pixel, receive mine
    const int myPx = col & 1;
    const int pix  = (y0 + row) * WW + x0 + col;
#pragma unroll
    for (int o = 0; o < 4; o++) {
        float sOwn = myPx ? sumS[1][o] : sumS[0][o];
        float sOth = myPx ? sumS[0][o] : sumS[1][o];
        float qOwn = myPx ? sumQ[1][o] : sumQ[0][o];
        float qOth = myPx ? sumQ[0][o] : sumQ[1][o];
        float S = sOwn + __shfl_xor_sync(0xFFFFFFFFu, sOth, 1);
        float Q = qOwn + __shfl_xor_sync(0xFFFFFFFFu, qOth, 1);
        float mn  = S * 0.0625f;
        float var = fmaxf((Q - 16.f * mn * mn) * (1.f / 15.f), 0.f);
        int oidx = (b * 4 + o) * HWP + pix;
        out[NOUT + oidx]     = var;              // EU
        out[2 * NOUT + oidx] = mn + lms[oidx];   // mean
    }

    // ---- au epilogue ----
    {
        float2 f01 = unpk(auA);
        float2 f23 = unpk(auB);
        float av[4] = { f01.x, f01.y, f23.x, f23.y };
#pragma unroll
        for (int o = 0; o < 4; o++)
            out[(b * 4 + o) * HWP + pix] = fast_sigmoid(av[o] + ba[o]);  // AU
    }
}

// ---------------------------------------------------------------------------
extern "C" void kernel_launch(void* const* d_in, const int* in_sizes, int n_in,
                              void* d_out, int out_size) {
    const float* x     = (const float*)d_in[0];
    const float* lms   = (const float*)d_in[1];
    const float* Wc    = (const float*)d_in[2];
    const float* bc    = (const float*)d_in[3];
    const float* Wo    = (const float*)d_in[4];
    const float* bo    = (const float*)d_in[5];
    const float* Wa    = (const float*)d_in[6];
    const float* ba    = (const float*)d_in[7];
    const float* masks = (const float*)d_in[8];
    float* out = (float*)d_out;

    cudaFuncSetAttribute(conv_hmma,
                         cudaFuncAttributeMaxDynamicSharedMemorySize, CV_SMEM);

    wprep<<<288, 256>>>(Wc);
    xprep<<<8192, 256>>>(x);
    conv_hmma<<<2048, 256, CV_SMEM>>>(bc);
    mcau_kernel<<<dim3(8, 32, 4), 256>>>(lms, Wo, bo, masks, Wa, ba, out);
}

// round 13
// speedup vs baseline: 2.2190x; 1.3531x over previous
#include <cuda_runtime.h>
#include <cuda_fp16.h>

#define BB 4
#define CIN 64
#define CO 128
#define HH 256
#define WW 256
#define HWP 65536
#define NOUT (BB*4*HWP)   // 1048576

typedef unsigned long long u64;

// scratch
__device__ float g_h[(size_t)BB * CO * HWP];                          // conv1 out fp32 [b][cout][pix]
__device__ __align__(256) unsigned short g_xh[(size_t)BB * HWP * 64]; // x fp16, [b][pix][ci]
__device__ __align__(256) unsigned char  g_wp[9 * 16384];             // conv weights fp16, swizzled
__device__ __align__(256) unsigned char  g_hf[(size_t)BB * HWP * 256];// h fp16 pixel-major [b][pix][c]
__device__ __align__(256) unsigned char  g_wm[64 * 256];              // Wm fp16, 256B-row swizzled
__device__ __align__(256) unsigned char  g_wau[9 * 16 * 256];         // Wau fp16 (rows 4-15 zero), swizzled

// ---- fast transcendentals --------------------------------------------------
__device__ __forceinline__ float fast_ex2(float x) {
    float e; asm("ex2.approx.f32 %0, %1;" : "=f"(e) : "f"(x)); return e;
}
__device__ __forceinline__ float fast_rcp(float x) {
    float r; asm("rcp.approx.f32 %0, %1;" : "=f"(r) : "f"(x)); return r;
}
__device__ __forceinline__ float fast_sigmoid(float x) {
    return fast_rcp(1.0f + fast_ex2(-x * 1.4426950408889634f));
}

// ---- cp.async helpers -----------------------------------------------------
__device__ __forceinline__ void cpa16(unsigned saddr, const void* gaddr) {
    asm volatile("cp.async.cg.shared.global [%0], [%1], 16;"
                 :: "r"(saddr), "l"(gaddr));
}
__device__ __forceinline__ void cpa16z(unsigned saddr, const void* gaddr, int ok) {
    asm volatile("cp.async.cg.shared.global [%0], [%1], 16, %2;"
                 :: "r"(saddr), "l"(gaddr), "r"(ok ? 16 : 0));
}
__device__ __forceinline__ void cpa_commit() {
    asm volatile("cp.async.commit_group;");
}
__device__ __forceinline__ void cpa_wait_all() {
    asm volatile("cp.async.wait_group 0;");
}

// ---- legacy tensor core ---------------------------------------------------
__device__ __forceinline__ void ldmx4(unsigned& r0, unsigned& r1,
                                      unsigned& r2, unsigned& r3, unsigned a) {
    asm volatile("ldmatrix.sync.aligned.m8n8.x4.shared.b16 {%0,%1,%2,%3}, [%4];"
                 : "=r"(r0), "=r"(r1), "=r"(r2), "=r"(r3) : "r"(a));
}
__device__ __forceinline__ void mma_f16(float* d, unsigned a0, unsigned a1,
                                        unsigned a2, unsigned a3,
                                        unsigned b0, unsigned b1) {
    asm volatile(
        "mma.sync.aligned.m16n8k16.row.col.f32.f16.f16.f32 "
        "{%0,%1,%2,%3}, {%4,%5,%6,%7}, {%8,%9}, {%0,%1,%2,%3};"
        : "+f"(d[0]), "+f"(d[1]), "+f"(d[2]), "+f"(d[3])
        : "r"(a0), "r"(a1), "r"(a2), "r"(a3), "r"(b0), "r"(b1));
}
__device__ __forceinline__ int swz(int off)    { return off ^ ((off >> 3) & 0x70); }
__device__ __forceinline__ int swz256(int off) { return off ^ (((off >> 8) & 7) << 4); }

// ---------------------------------------------------------------------------
// Prep kernels
// ---------------------------------------------------------------------------
__global__ void wprep(const float* __restrict__ Wc) {
    int i = blockIdx.x * 256 + threadIdx.x;   // < 73728
    int tap = i >> 13, rem = i & 8191, cout = rem >> 6, ci = rem & 63;
    __half h = __float2half_rn(Wc[cout * 576 + ci * 9 + tap]);
    *(unsigned short*)(g_wp + tap * 16384 + swz(cout * 128 + ci * 2)) =
        *reinterpret_cast<unsigned short*>(&h);
}

__global__ void xprep(const float* __restrict__ x) {
    __shared__ unsigned short shh[32 * 66];
    const int bx = blockIdx.x;
    const int b = bx >> 11;
    const int px0 = (bx & 2047) * 32;
    const int tid = threadIdx.x;
    for (int i = tid; i < 2048; i += 256) {
        int ci = i >> 5, p = i & 31;
        __half h = __float2half_rn(x[(((size_t)b * 64 + ci) << 16) + px0 + p]);
        shh[p * 66 + ci] = *reinterpret_cast<unsigned short*>(&h);
    }
    __syncthreads();
    for (int i = tid; i < 1024; i += 256) {
        int p = i >> 5, j = i & 31;
        unsigned vh = shh[p * 66 + 2 * j] | ((unsigned)shh[p * 66 + 2 * j + 1] << 16);
        reinterpret_cast<unsigned*>(g_xh)[((size_t)b * HWP + px0 + p) * 32 + j] = vh;
    }
}

// Wm[r = t*4+o][c] = Wo[o][c]*mask[t][c], fp16, 256B-row swizzle
__global__ void wmprep(const float* __restrict__ Wo, const float* __restrict__ masks) {
    int i = blockIdx.x * 256 + threadIdx.x;   // < 8192
    int r = i >> 7, c = i & 127, t = r >> 2, o = r & 3;
    __half h = __float2half_rn(Wo[o * 128 + c] * masks[t * 128 + c]);
    *(unsigned short*)(g_wm + r * 256 + ((c * 2) ^ ((r & 7) << 4))) =
        *reinterpret_cast<unsigned short*>(&h);
}

// Wau[tap][r][c]: rows 0-3 = Wa[o][c][tap], rows 4-15 zero
__global__ void wauprep(const float* __restrict__ Wa) {
    int i = blockIdx.x * 256 + threadIdx.x;   // < 18432
    int tap = i >> 11, rem = i & 2047, r = rem >> 7, c = rem & 127;
    float v = (r < 4) ? Wa[(r * 128 + c) * 9 + tap] : 0.f;
    __half h = __float2half_rn(v);
    *(unsigned short*)(g_wau + tap * 4096 + r * 256 + ((c * 2) ^ ((r & 7) << 4))) =
        *reinterpret_cast<unsigned short*>(&h);
}

// h fp32 [b][cout][pix] -> fp16 pixel-major g_hf[b][pix][c]
__global__ void hprep() {
    __shared__ unsigned short sh[32 * 130];
    const int blk = blockIdx.x;
    const int b = blk >> 11;
    const int px0 = (blk & 2047) * 32;
    const int tid = threadIdx.x;
    for (int i = tid; i < 4096; i += 256) {
        int cout = i >> 5, p = i & 31;
        __half h = __float2half_rn(g_h[((size_t)(b * CO + cout) << 16) + px0 + p]);
        sh[p * 130 + cout] = *reinterpret_cast<unsigned short*>(&h);
    }
    __syncthreads();
    for (int i = tid; i < 2048; i += 256) {
        int p = i >> 6, j = i & 63;
        unsigned u = sh[p * 130 + 2 * j] | ((unsigned)sh[p * 130 + 2 * j + 1] << 16);
        reinterpret_cast<unsigned*>(g_hf)[((size_t)b * HWP + px0 + p) * 64 + j] = u;
    }
}

// ---------------------------------------------------------------------------
// Kernel 1: conv1 via mma.sync fp16 single-pass (unchanged from R12).
// ---------------------------------------------------------------------------
#define SB_BYTES 49920
#define CV_SMEM (SB_BYTES + 32768 + 1024)

__global__ __launch_bounds__(256, 2) void conv_hmma(const float* __restrict__ bc) {
    extern __shared__ unsigned char dsm[];
    const int tid = threadIdx.x;
    const int w = tid >> 5, lane = tid & 31;
    const int blk = blockIdx.x;
    const int xh = blk & 1, y = (blk >> 1) & 255, b = blk >> 9;
    const int x0 = xh * 128;

    unsigned raw = (unsigned)__cvta_generic_to_shared(dsm);
    unsigned base = (raw + 1023) & ~1023u;
    unsigned sBh = base, sA = base + SB_BYTES;

    for (int i = tid; i < 3120; i += 256) {
        int r = i >> 3, c = i & 7;
        int ky = r / 130, p = r % 130;
        int gy = y + ky - 1, gx = x0 + p - 1;
        int ok = (gy >= 0 && gy < HH && gx >= 0 && gx < WW);
        const unsigned char* src = (const unsigned char*)g_xh
            + ((size_t)(b * HWP + (ok ? gy * WW + gx : 0)) * 128) + c * 16;
        cpa16z(sBh + swz(r * 128 + c * 16), src, ok);
    }
    cpa_commit();

    auto prefA = [&](int t, int buf) {
        const unsigned char* src = g_wp + t * 16384;
        unsigned dst = sA + buf * 16384;
#pragma unroll
        for (int j = 0; j < 4; j++) {
            int off = (tid * 4 + j) * 16;
            cpa16(dst + off, src + off);
        }
        cpa_commit();
    };
    prefA(0, 0);

    const int arow = (16 * w + (lane & 7) + ((lane >> 3) & 1) * 8) * 128
                   + ((lane >> 4) & 1) * 16;
    const int pxl  = (lane & 7) + ((lane >> 4) & 1) * 8;
    const int kextB = ((lane >> 3) & 1) * 16;

    float d[16][4];
#pragma unroll
    for (int j = 0; j < 16; j++)
#pragma unroll
        for (int q = 0; q < 4; q++) d[j][q] = 0.f;

    for (int t = 0; t < 9; t++) {
        cpa_wait_all();
        __syncthreads();
        if (t < 8) prefA(t + 1, (t + 1) & 1);

        const int rowb = (t / 3) * 130 + (t % 3);
        unsigned Abuf = sA + (t & 1) * 16384;
#pragma unroll
        for (int k = 0; k < 4; k++) {
            unsigned a0, a1, a2, a3;
            ldmx4(a0, a1, a2, a3, Abuf + swz(arow + k * 32));
            const int bc0 = (rowb + pxl) * 128 + k * 32 + kextB;
#pragma unroll
            for (int jp = 0; jp < 8; jp++) {
                unsigned b0, b1, b2, b3;
                ldmx4(b0, b1, b2, b3, sBh + swz(bc0 + jp * 2048));
                mma_f16(d[2 * jp],     a0, a1, a2, a3, b0, b1);
                mma_f16(d[2 * jp + 1], a0, a1, a2, a3, b2, b3);
            }
        }
        __syncthreads();
    }

    const int g = lane >> 2, c2 = (lane & 3) * 2;
    const int cout0 = 16 * w + g;
    const float bias0 = bc[cout0], bias1 = bc[cout0 + 8];
    float* h0 = g_h + ((size_t)(b * CO + cout0) << 16) + y * WW + x0 + c2;
    float* h1 = h0 + ((size_t)8 << 16);
#pragma unroll
    for (int j = 0; j < 16; j++) {
        float2 v0 = make_float2(d[j][0] + bias0, d[j][1] + bias0);
        float2 v1 = make_float2(d[j][2] + bias1, d[j][3] + bias1);
        *reinterpret_cast<float2*>(h0 + j * 8) = v0;
        *reinterpret_cast<float2*>(h1 + j * 8) = v1;
    }
}

// ---------------------------------------------------------------------------
// Kernel 2: mc + au on HMMA. CTA = (b, y, xh): 128 px.
// h-tile: 3 rows x 130 px x 256B fp16 in smem (swz256).
// mc: Wm[64,128]@h (center tap); au: 9 taps Wau[16,128]@h.
// D -> smem [px][68 floats] -> batched-rcp tanh epilogue (2 threads/px).
// ---------------------------------------------------------------------------
#define H_TILE 99840                 // 390 * 256
#define MC_SMEM (H_TILE + 16384 + 36864 + 1024)

__global__ __launch_bounds__(256, 1) void mcau_hmma(
    const float* __restrict__ lms, const float* __restrict__ bo,
    const float* __restrict__ ba, float* __restrict__ out)
{
    extern __shared__ unsigned char dsm2[];
    const int tid = threadIdx.x;
    const int w = tid >> 5, lane = tid & 31;
    const int blk = blockIdx.x;
    const int xh = blk & 1, y = (blk >> 1) & 255, b = blk >> 9;
    const int x0 = xh * 128;

    unsigned raw = (unsigned)__cvta_generic_to_shared(dsm2);
    unsigned base = (raw + 1023) & ~1023u;
    unsigned char* smbase = dsm2 + (base - raw);
    unsigned sH = base, sWm = base + H_TILE, sWau = sWm + 16384;

    // ---- fills ----
    for (int i = tid; i < 6240; i += 256) {          // h tile: 390 rows x 16 chunks
        int r = i >> 4, c16 = i & 15;
        int ky = r / 130, p = r % 130;
        int gy = y + ky - 1, gx = x0 + p - 1;
        int ok = (gy >= 0 && gy < HH && gx >= 0 && gx < WW);
        const unsigned char* src = g_hf
            + ((size_t)(b * HWP + (ok ? gy * WW + gx : 0)) * 256) + c16 * 16;
        cpa16z(sH + swz256(r * 256 + c16 * 16), src, ok);
    }
    for (int i = tid; i < 3328; i += 256) {          // Wm 1024 + Wau 2304 (16B units)
        if (i < 1024) cpa16(sWm + i * 16, g_wm + i * 16);
        else {
            int j = i - 1024;
            cpa16(sWau + j * 16, g_wau + j * 16);
        }
    }
    cpa_commit();
    cpa_wait_all();
    __syncthreads();

    // ---- MMAs: warp owns 16 px (2 n8 tiles) ----
    const int n0 = w * 16;
    const int pxl  = (lane & 7) + ((lane >> 4) & 1) * 8;
    const int kextB = ((lane >> 3) & 1) * 16;
    const int arowl = ((lane & 7) + ((lane >> 3) & 1) * 8) * 256
                    + ((lane >> 4) & 1) * 16;

    float dmc[4][2][4], dau[2][4];
#pragma unroll
    for (int m = 0; m < 4; m++)
#pragma unroll
        for (int nt = 0; nt < 2; nt++)
#pragma unroll
            for (int q = 0; q < 4; q++) dmc[m][nt][q] = 0.f;
#pragma unroll
    for (int nt = 0; nt < 2; nt++)
#pragma unroll
        for (int q = 0; q < 4; q++) dau[nt][q] = 0.f;

#pragma unroll
    for (int tap = 0; tap < 9; tap++) {
        const int rowb = (tap / 3) * 130 + (tap % 3);
#pragma unroll
        for (int k = 0; k < 8; k++) {
            unsigned b0, b1, b2, b3;
            ldmx4(b0, b1, b2, b3,
                  sH + swz256((rowb + n0 + pxl) * 256 + k * 32 + kextB));
            unsigned a0, a1, a2, a3;
            ldmx4(a0, a1, a2, a3, sWau + tap * 4096 + swz256(arowl + k * 32));
            mma_f16(dau[0], a0, a1, a2, a3, b0, b1);
            mma_f16(dau[1], a0, a1, a2, a3, b2, b3);
            if (tap == 4) {                          // center tap -> mc GEMM
#pragma unroll
                for (int m = 0; m < 4; m++) {
                    unsigned m0, m1, m2, m3;
                    ldmx4(m0, m1, m2, m3,
                          sWm + swz256(m * 4096 + arowl + k * 32));
                    mma_f16(dmc[m][0], m0, m1, m2, m3, b0, b1);
                    mma_f16(dmc[m][1], m0, m1, m2, m3, b2, b3);
                }
            }
        }
    }
    __syncthreads();   // everyone done reading sH

    // ---- store D to smem overlay: sD[px][68 floats] (stride 272B) ----
    float* sD = reinterpret_cast<float*>(smbase);
    const int g = lane >> 2, c2 = (lane & 3) * 2;
#pragma unroll
    for (int m = 0; m < 4; m++)
#pragma unroll
        for (int nt = 0; nt < 2; nt++) {
            int pxb = n0 + nt * 8 + c2;
            int r = m * 16 + g;
            sD[pxb * 68 + r]           = dmc[m][nt][0];
            sD[(pxb + 1) * 68 + r]     = dmc[m][nt][1];
            sD[pxb * 68 + r + 8]       = dmc[m][nt][2];
            sD[(pxb + 1) * 68 + r + 8] = dmc[m][nt][3];
        }
    if (g < 4) {
#pragma unroll
        for (int nt = 0; nt < 2; nt++) {
            int pxb = n0 + nt * 8 + c2;
            sD[pxb * 68 + 64 + g]       = dau[nt][0];
            sD[(pxb + 1) * 68 + 64 + g] = dau[nt][1];
        }
    }
    __syncthreads();

    // ---- epilogue: 2 threads per px, t-split 8/8, batched-rcp tanh ----
    const int px = tid >> 1, half = tid & 1;
    const float* dp = sD + px * 68 + half * 32;
    float vals[32];
#pragma unroll
    for (int q = 0; q < 8; q++) {
        float4 v4 = reinterpret_cast<const float4*>(dp)[q];
        vals[4 * q] = v4.x; vals[4 * q + 1] = v4.y;
        vals[4 * q + 2] = v4.z; vals[4 * q + 3] = v4.w;
    }
    const float bov[4] = { bo[0], bo[1], bo[2], bo[3] };
    float sumS[4] = {0.f, 0.f, 0.f, 0.f}, sumQ[4] = {0.f, 0.f, 0.f, 0.f};
#pragma unroll
    for (int g4 = 0; g4 < 4; g4++) {
        float dd[8];
#pragma unroll
        for (int i = 0; i < 8; i++) {
            float v = vals[g4 * 8 + i] + bov[i & 3];
            float xc = fminf(v, 4.8f);               // cap keeps group product finite
            dd[i] = 1.0f + fast_ex2(xc * 2.8853900817779268f);
        }
        float p01 = dd[0] * dd[1], p23 = dd[2] * dd[3];
        float p45 = dd[4] * dd[5], p67 = dd[6] * dd[7];
        float p0123 = p01 * p23, p4567 = p45 * p67;
        float r = fast_rcp(p0123 * p4567);
        float r0123 = r * p4567, r4567 = r * p0123;
        float i01 = r0123 * p23, i23 = r0123 * p01;
        float i45 = r4567 * p67, i67 = r4567 * p45;
        float inv[8];
        inv[0] = i01 * dd[1]; inv[1] = i01 * dd[0];
        inv[2] = i23 * dd[3]; inv[3] = i23 * dd[2];
        inv[4] = i45 * dd[5]; inv[5] = i45 * dd[4];
        inv[6] = i67 * dd[7]; inv[7] = i67 * dd[6];
#pragma unroll
        for (int i = 0; i < 8; i++) {
            float s = fmaf(-2.f, inv[i], 1.f);       // tanh
            int o = i & 3;
            sumS[o] += s;
            sumQ[o] = fmaf(s, s, sumQ[o]);
        }
    }

    const int pix = y * WW + x0 + px;
#pragma unroll
    for (int o = 0; o < 4; o++) {
        float S = sumS[o] + __shfl_xor_sync(0xFFFFFFFFu, sumS[o], 1);
        float Q = sumQ[o] + __shfl_xor_sync(0xFFFFFFFFu, sumQ[o], 1);
        if ((o >> 1) == half) {
            float mn  = S * 0.0625f;
            float var = fmaxf((Q - 16.f * mn * mn) * (1.f / 15.f), 0.f);
            int oidx = (b * 4 + o) * HWP + pix;
            out[NOUT + oidx]     = var;              // EU
            out[2 * NOUT + oidx] = mn + lms[oidx];   // mean
        }
    }
    if (half == 0) {                                 // AU
#pragma unroll
        for (int o = 0; o < 4; o++) {
            float v = sD[px * 68 + 64 + o];
            out[(b * 4 + o) * HWP + pix] = fast_sigmoid(v + ba[o]);
        }
    }
}

// ---------------------------------------------------------------------------
extern "C" void kernel_launch(void* const* d_in, const int* in_sizes, int n_in,
                              void* d_out, int out_size) {
    const float* x     = (const float*)d_in[0];
    const float* lms   = (const float*)d_in[1];
    const float* Wc    = (const float*)d_in[2];
    const float* bc    = (const float*)d_in[3];
    const float* Wo    = (const float*)d_in[4];
    const float* bo    = (const float*)d_in[5];
    const float* Wa    = (const float*)d_in[6];
    const float* ba    = (const float*)d_in[7];
    const float* masks = (const float*)d_in[8];
    float* out = (float*)d_out;

    cudaFuncSetAttribute(conv_hmma,
                         cudaFuncAttributeMaxDynamicSharedMemorySize, CV_SMEM);
    cudaFuncSetAttribute(mcau_hmma,
                         cudaFuncAttributeMaxDynamicSharedMemorySize, MC_SMEM);

    wprep<<<288, 256>>>(Wc);
    xprep<<<8192, 256>>>(x);
    wmprep<<<32, 256>>>(Wo, masks);
    wauprep<<<72, 256>>>(Wa);
    conv_hmma<<<2048, 256, CV_SMEM>>>(bc);
    hprep<<<8192, 256>>>();
    mcau_hmma<<<2048, 256, MC_SMEM>>>(lms, bo, ba, out);
}

// round 15
// speedup vs baseline: 2.9151x; 1.3137x over previous
#include <cuda_runtime.h>
#include <cuda_fp16.h>

#define BB 4
#define CIN 64
#define CO 128
#define HH 256
#define WW 256
#define HWP 65536
#define NOUT (BB*4*HWP)   // 1048576

typedef unsigned long long u64;

// scratch
__device__ __align__(256) unsigned short g_xh[(size_t)BB * HWP * 64]; // x fp16, [b][pix][ci]
__device__ __align__(256) unsigned char  g_wp[9 * 16384];             // conv weights fp16, swizzled
__device__ __align__(256) unsigned char  g_hf[(size_t)BB * HWP * 256];// h fp16 pixel-major [b][pix][c]
__device__ __align__(256) unsigned char  g_wm[64 * 256];              // Wm fp16, 256B-row swizzled
__device__ __align__(256) unsigned char  g_wau[9 * 16 * 256];         // Wau fp16 (rows 4-15 zero), swizzled

// ---- fast transcendentals --------------------------------------------------
__device__ __forceinline__ float fast_ex2(float x) {
    float e; asm("ex2.approx.f32 %0, %1;" : "=f"(e) : "f"(x)); return e;
}
__device__ __forceinline__ float fast_rcp(float x) {
    float r; asm("rcp.approx.f32 %0, %1;" : "=f"(r) : "f"(x)); return r;
}
__device__ __forceinline__ float fast_sigmoid(float x) {
    return fast_rcp(1.0f + fast_ex2(-x * 1.4426950408889634f));
}

// ---- cp.async helpers -----------------------------------------------------
__device__ __forceinline__ void cpa16(unsigned saddr, const void* gaddr) {
    asm volatile("cp.async.cg.shared.global [%0], [%1], 16;"
                 :: "r"(saddr), "l"(gaddr));
}
__device__ __forceinline__ void cpa16z(unsigned saddr, const void* gaddr, int ok) {
    asm volatile("cp.async.cg.shared.global [%0], [%1], 16, %2;"
                 :: "r"(saddr), "l"(gaddr), "r"(ok ? 16 : 0));
}
__device__ __forceinline__ void cpa_commit() {
    asm volatile("cp.async.commit_group;");
}
__device__ __forceinline__ void cpa_wait_all() {
    asm volatile("cp.async.wait_group 0;");
}

// ---- legacy tensor core ---------------------------------------------------
__device__ __forceinline__ void ldmx4(unsigned& r0, unsigned& r1,
                                      unsigned& r2, unsigned& r3, unsigned a) {
    asm volatile("ldmatrix.sync.aligned.m8n8.x4.shared.b16 {%0,%1,%2,%3}, [%4];"
                 : "=r"(r0), "=r"(r1), "=r"(r2), "=r"(r3) : "r"(a));
}
__device__ __forceinline__ void mma_f16(float* d, unsigned a0, unsigned a1,
                                        unsigned a2, unsigned a3,
                                        unsigned b0, unsigned b1) {
    asm volatile(
        "mma.sync.aligned.m16n8k16.row.col.f32.f16.f16.f32 "
        "{%0,%1,%2,%3}, {%4,%5,%6,%7}, {%8,%9}, {%0,%1,%2,%3};"
        : "+f"(d[0]), "+f"(d[1]), "+f"(d[2]), "+f"(d[3])
        : "r"(a0), "r"(a1), "r"(a2), "r"(a3), "r"(b0), "r"(b1));
}
__device__ __forceinline__ int swz(int off)    { return off ^ ((off >> 3) & 0x70); }
__device__ __forceinline__ int swz256(int off) { return off ^ (((off >> 8) & 7) << 4); }

// ---------------------------------------------------------------------------
// Prep A (fused): conv weights + Wm + Wau -> fp16 swizzled tiles. grid 392.
// ---------------------------------------------------------------------------
__global__ void allwprep(const float* __restrict__ Wc, const float* __restrict__ Wo,
                         const float* __restrict__ masks, const float* __restrict__ Wa) {
    const int blk = blockIdx.x, tid = threadIdx.x;
    if (blk < 288) {                       // conv weights: 73728 elems
        int i = blk * 256 + tid;
        int tap = i >> 13, rem = i & 8191, cout = rem >> 6, ci = rem & 63;
        __half h = __float2half_rn(Wc[cout * 576 + ci * 9 + tap]);
        *(unsigned short*)(g_wp + tap * 16384 + swz(cout * 128 + ci * 2)) =
            *reinterpret_cast<unsigned short*>(&h);
    } else if (blk < 320) {                // Wm: 8192 elems
        int i = (blk - 288) * 256 + tid;
        int r = i >> 7, c = i & 127, t = r >> 2, o = r & 3;
        __half h = __float2half_rn(Wo[o * 128 + c] * masks[t * 128 + c]);
        *(unsigned short*)(g_wm + r * 256 + ((c * 2) ^ ((r & 7) << 4))) =
            *reinterpret_cast<unsigned short*>(&h);
    } else {                               // Wau: 18432 elems
        int i = (blk - 320) * 256 + tid;
        int tap = i >> 11, rem = i & 2047, r = rem >> 7, c = rem & 127;
        float v = (r < 4) ? Wa[(r * 128 + c) * 9 + tap] : 0.f;
        __half h = __float2half_rn(v);
        *(unsigned short*)(g_wau + tap * 4096 + r * 256 + ((c * 2) ^ ((r & 7) << 4))) =
            *reinterpret_cast<unsigned short*>(&h);
    }
}

// ---------------------------------------------------------------------------
// Prep B: transpose x to pixel-major fp16: g_xh[b][pix][ci]
// ---------------------------------------------------------------------------
__global__ void xprep(const float* __restrict__ x) {
    __shared__ unsigned short shh[32 * 66];
    const int bx = blockIdx.x;
    const int b = bx >> 11;
    const int px0 = (bx & 2047) * 32;
    const int tid = threadIdx.x;
    for (int i = tid; i < 2048; i += 256) {
        int ci = i >> 5, p = i & 31;
        __half h = __float2half_rn(x[(((size_t)b * 64 + ci) << 16) + px0 + p]);
        shh[p * 66 + ci] = *reinterpret_cast<unsigned short*>(&h);
    }
    __syncthreads();
    for (int i = tid; i < 1024; i += 256) {
        int p = i >> 5, j = i & 31;
        unsigned vh = shh[p * 66 + 2 * j] | ((unsigned)shh[p * 66 + 2 * j + 1] << 16);
        reinterpret_cast<unsigned*>(g_xh)[((size_t)b * HWP + px0 + p) * 32 + j] = vh;
    }
}

// ---------------------------------------------------------------------------
// Kernel 1: conv1 via mma.sync fp16, epilogue writes g_hf DIRECTLY
// (fp16 pixel-major via smem staging; fp32 h round-trip eliminated).
// ---------------------------------------------------------------------------
#define SB_BYTES 49920
#define CV_SMEM (SB_BYTES + 32768 + 1024)
#define STG_PITCH 272     // 17*16: 16B-aligned rows, conflict-free STS.16 scatter

__global__ __launch_bounds__(256, 2) void conv_hmma(const float* __restrict__ bc) {
    extern __shared__ unsigned char dsm[];
    const int tid = threadIdx.x;
    const int w = tid >> 5, lane = tid & 31;
    const int blk = blockIdx.x;
    const int xh = blk & 1, y = (blk >> 1) & 255, b = blk >> 9;
    const int x0 = xh * 128;

    unsigned raw = (unsigned)__cvta_generic_to_shared(dsm);
    unsigned base = (raw + 1023) & ~1023u;
    unsigned char* smbase = dsm + (base - raw);
    unsigned sBh = base, sA = base + SB_BYTES;

    for (int i = tid; i < 3120; i += 256) {
        int r = i >> 3, c = i & 7;
        int ky = r / 130, p = r % 130;
        int gy = y + ky - 1, gx = x0 + p - 1;
        int ok = (gy >= 0 && gy < HH && gx >= 0 && gx < WW);
        const unsigned char* src = (const unsigned char*)g_xh
            + ((size_t)(b * HWP + (ok ? gy * WW + gx : 0)) * 128) + c * 16;
        cpa16z(sBh + swz(r * 128 + c * 16), src, ok);
    }
    cpa_commit();

    auto prefA = [&](int t, int buf) {
        const unsigned char* src = g_wp + t * 16384;
        unsigned dst = sA + buf * 16384;
#pragma unroll
        for (int j = 0; j < 4; j++) {
            int off = (tid * 4 + j) * 16;
            cpa16(dst + off, src + off);
        }
        cpa_commit();
    };
    prefA(0, 0);

    const int arow = (16 * w + (lane & 7) + ((lane >> 3) & 1) * 8) * 128
                   + ((lane >> 4) & 1) * 16;
    const int pxl  = (lane & 7) + ((lane >> 4) & 1) * 8;
    const int kextB = ((lane >> 3) & 1) * 16;

    float d[16][4];
#pragma unroll
    for (int j = 0; j < 16; j++)
#pragma unroll
        for (int q = 0; q < 4; q++) d[j][q] = 0.f;

    for (int t = 0; t < 9; t++) {
        cpa_wait_all();
        __syncthreads();
        if (t < 8) prefA(t + 1, (t + 1) & 1);

        const int rowb = (t / 3) * 130 + (t % 3);
        unsigned Abuf = sA + (t & 1) * 16384;
#pragma unroll
        for (int k = 0; k < 4; k++) {
            unsigned a0, a1, a2, a3;
            ldmx4(a0, a1, a2, a3, Abuf + swz(arow + k * 32));
            const int bc0 = (rowb + pxl) * 128 + k * 32 + kextB;
#pragma unroll
            for (int jp = 0; jp < 8; jp++) {
                unsigned b0, b1, b2, b3;
                ldmx4(b0, b1, b2, b3, sBh + swz(bc0 + jp * 2048));
                mma_f16(d[2 * jp],     a0, a1, a2, a3, b0, b1);
                mma_f16(d[2 * jp + 1], a0, a1, a2, a3, b2, b3);
            }
        }
        __syncthreads();
    }
    // after final barrier: sBh region free -> reuse as fp16 pixel-major staging

    const int g = lane >> 2, c2 = (lane & 3) * 2;
    const int cout0 = 16 * w + g;
    const float bias0 = bc[cout0], bias1 = bc[cout0 + 8];
    // fragment scatter: sS[px * 272 + cout * 2]
#pragma unroll
    for (int j = 0; j < 16; j++) {
        int px = j * 8 + c2;
        __half v00 = __float2half_rn(d[j][0] + bias0);
        __half v01 = __float2half_rn(d[j][1] + bias0);
        __half v10 = __float2half_rn(d[j][2] + bias1);
        __half v11 = __float2half_rn(d[j][3] + bias1);
        *(__half*)(smbase + px * STG_PITCH + cout0 * 2)             = v00;
        *(__half*)(smbase + (px + 1) * STG_PITCH + cout0 * 2)       = v01;
        *(__half*)(smbase + px * STG_PITCH + (cout0 + 8) * 2)       = v10;
        *(__half*)(smbase + (px + 1) * STG_PITCH + (cout0 + 8) * 2) = v11;
    }
    __syncthreads();

    // coalesced copy: 128 px x 256 B -> g_hf[b][pix][c]
    unsigned char* dstbase = g_hf + ((size_t)(b * HWP + y * WW + x0)) * 256;
#pragma unroll
    for (int jj = 0; jj < 8; jj++) {
        int i = jj * 256 + tid;          // < 2048
        int px = i >> 4, c16 = i & 15;
        uint4 v = *reinterpret_cast<const uint4*>(smbase + px * STG_PITCH + c16 * 16);
        *reinterpret_cast<uint4*>(dstbase + px * 256 + c16 * 16) = v;
    }
}

// ---------------------------------------------------------------------------
// Kernel 2: mc + au on HMMA (unchanged from R13).
// ---------------------------------------------------------------------------
#define H_TILE 99840                 // 390 * 256
#define MC_SMEM (H_TILE + 16384 + 36864 + 1024)

__global__ __launch_bounds__(256, 1) void mcau_hmma(
    const float* __restrict__ lms, const float* __restrict__ bo,
    const float* __restrict__ ba, float* __restrict__ out)
{
    extern __shared__ unsigned char dsm2[];
    const int tid = threadIdx.x;
    const int w = tid >> 5, lane = tid & 31;
    const int blk = blockIdx.x;
    const int xh = blk & 1, y = (blk >> 1) & 255, b = blk >> 9;
    const int x0 = xh * 128;

    unsigned raw = (unsigned)__cvta_generic_to_shared(dsm2);
    unsigned base = (raw + 1023) & ~1023u;
    unsigned char* smbase = dsm2 + (base - raw);
    unsigned sH = base, sWm = base + H_TILE, sWau = sWm + 16384;

    for (int i = tid; i < 6240; i += 256) {
        int r = i >> 4, c16 = i & 15;
        int ky = r / 130, p = r % 130;
        int gy = y + ky - 1, gx = x0 + p - 1;
        int ok = (gy >= 0 && gy < HH && gx >= 0 && gx < WW);
        const unsigned char* src = g_hf
            + ((size_t)(b * HWP + (ok ? gy * WW + gx : 0)) * 256) + c16 * 16;
        cpa16z(sH + swz256(r * 256 + c16 * 16), src, ok);
    }
    for (int i = tid; i < 3328; i += 256) {
        if (i < 1024) cpa16(sWm + i * 16, g_wm + i * 16);
        else {
            int j = i - 1024;
            cpa16(sWau + j * 16, g_wau + j * 16);
        }
    }
    cpa_commit();
    cpa_wait_all();
    __syncthreads();

    const int n0 = w * 16;
    const int pxl  = (lane & 7) + ((lane >> 4) & 1) * 8;
    const int kextB = ((lane >> 3) & 1) * 16;
    const int arowl = ((lane & 7) + ((lane >> 3) & 1) * 8) * 256
                    + ((lane >> 4) & 1) * 16;

    float dmc[4][2][4], dau[2][4];
#pragma unroll
    for (int m = 0; m < 4; m++)
#pragma unroll
        for (int nt = 0; nt < 2; nt++)
#pragma unroll
            for (int q = 0; q < 4; q++) dmc[m][nt][q] = 0.f;
#pragma unroll
    for (int nt = 0; nt < 2; nt++)
#pragma unroll
        for (int q = 0; q < 4; q++) dau[nt][q] = 0.f;

#pragma unroll
    for (int tap = 0; tap < 9; tap++) {
        const int rowb = (tap / 3) * 130 + (tap % 3);
#pragma unroll
        for (int k = 0; k < 8; k++) {
            unsigned b0, b1, b2, b3;
            ldmx4(b0, b1, b2, b3,
                  sH + swz256((rowb + n0 + pxl) * 256 + k * 32 + kextB));
            unsigned a0, a1, a2, a3;
            ldmx4(a0, a1, a2, a3, sWau + tap * 4096 + swz256(arowl + k * 32));
            mma_f16(dau[0], a0, a1, a2, a3, b0, b1);
            mma_f16(dau[1], a0, a1, a2, a3, b2, b3);
            if (tap == 4) {
#pragma unroll
                for (int m = 0; m < 4; m++) {
                    unsigned m0, m1, m2, m3;
                    ldmx4(m0, m1, m2, m3,
                          sWm + swz256(m * 4096 + arowl + k * 32));
                    mma_f16(dmc[m][0], m0, m1, m2, m3, b0, b1);
                    mma_f16(dmc[m][1], m0, m1, m2, m3, b2, b3);
                }
            }
        }
    }
    __syncthreads();

    float* sD = reinterpret_cast<float*>(smbase);
    const int g = lane >> 2, c2 = (lane & 3) * 2;
#pragma unroll
    for (int m = 0; m < 4; m++)
#pragma unroll
        for (int nt = 0; nt < 2; nt++) {
            int pxb = n0 + nt * 8 + c2;
            int r = m * 16 + g;
            sD[pxb * 68 + r]           = dmc[m][nt][0];
            sD[(pxb + 1) * 68 + r]     = dmc[m][nt][1];
            sD[pxb * 68 + r + 8]       = dmc[m][nt][2];
            sD[(pxb + 1) * 68 + r + 8] = dmc[m][nt][3];
        }
    if (g < 4) {
#pragma unroll
        for (int nt = 0; nt < 2; nt++) {
            int pxb = n0 + nt * 8 + c2;
            sD[pxb * 68 + 64 + g]       = dau[nt][0];
            sD[(pxb + 1) * 68 + 64 + g] = dau[nt][1];
        }
    }
    __syncthreads();

    const int px = tid >> 1, half = tid & 1;
    const float* dp = sD + px * 68 + half * 32;
    float vals[32];
#pragma unroll
    for (int q = 0; q < 8; q++) {
        float4 v4 = reinterpret_cast<const float4*>(dp)[q];
        vals[4 * q] = v4.x; vals[4 * q + 1] = v4.y;
        vals[4 * q + 2] = v4.z; vals[4 * q + 3] = v4.w;
    }
    const float bov[4] = { bo[0], bo[1], bo[2], bo[3] };
    float sumS[4] = {0.f, 0.f, 0.f, 0.f}, sumQ[4] = {0.f, 0.f, 0.f, 0.f};
#pragma unroll
    for (int g4 = 0; g4 < 4; g4++) {
        float dd[8];
#pragma unroll
        for (int i = 0; i < 8; i++) {
            float v = vals[g4 * 8 + i] + bov[i & 3];
            float xc = fminf(v, 4.8f);
            dd[i] = 1.0f + fast_ex2(xc * 2.8853900817779268f);
        }
        float p01 = dd[0] * dd[1], p23 = dd[2] * dd[3];
        float p45 = dd[4] * dd[5], p67 = dd[6] * dd[7];
        float p0123 = p01 * p23, p4567 = p45 * p67;
        float r = fast_rcp(p0123 * p4567);
        float r0123 = r * p4567, r4567 = r * p0123;
        float i01 = r0123 * p23, i23 = r0123 * p01;
        float i45 = r4567 * p67, i67 = r4567 * p45;
        float inv[8];
        inv[0] = i01 * dd[1]; inv[1] = i01 * dd[0];
        inv[2] = i23 * dd[3]; inv[3] = i23 * dd[2];
        inv[4] = i45 * dd[5]; inv[5] = i45 * dd[4];
        inv[6] = i67 * dd[7]; inv[7] = i67 * dd[6];
#pragma unroll
        for (int i = 0; i < 8; i++) {
            float s = fmaf(-2.f, inv[i], 1.f);
            int o = i & 3;
            sumS[o] += s;
            sumQ[o] = fmaf(s, s, sumQ[o]);
        }
    }

    const int pix = y * WW + x0 + px;
#pragma unroll
    for (int o = 0; o < 4; o++) {
        float S = sumS[o] + __shfl_xor_sync(0xFFFFFFFFu, sumS[o], 1);
        float Q = sumQ[o] + __shfl_xor_sync(0xFFFFFFFFu, sumQ[o], 1);
        if ((o >> 1) == half) {
            float mn  = S * 0.0625f;
            float var = fmaxf((Q - 16.f * mn * mn) * (1.f / 15.f), 0.f);
            int oidx = (b * 4 + o) * HWP + pix;
            out[NOUT + oidx]     = var;              // EU
            out[2 * NOUT + oidx] = mn + lms[oidx];   // mean
        }
    }
    if (half == 0) {                                 // AU
#pragma unroll
        for (int o = 0; o < 4; o++) {
            float v = sD[px * 68 + 64 + o];
            out[(b * 4 + o) * HWP + pix] = fast_sigmoid(v + ba[o]);
        }
    }
}

// ---------------------------------------------------------------------------
extern "C" void kernel_launch(void* const* d_in, const int* in_sizes, int n_in,
                              void* d_out, int out_size) {
    const float* x     = (const float*)d_in[0];
    const float* lms   = (const float*)d_in[1];
    const float* Wc    = (const float*)d_in[2];
    const float* bc    = (const float*)d_in[3];
    const float* Wo    = (const float*)d_in[4];
    const float* bo    = (const float*)d_in[5];
    const float* Wa    = (const float*)d_in[6];
    const float* ba    = (const float*)d_in[7];
    const float* masks = (const float*)d_in[8];
    float* out = (float*)d_out;

    cudaFuncSetAttribute(conv_hmma,
                         cudaFuncAttributeMaxDynamicSharedMemorySize, CV_SMEM);
    cudaFuncSetAttribute(mcau_hmma,
                         cudaFuncAttributeMaxDynamicSharedMemorySize, MC_SMEM);

    allwprep<<<392, 256>>>(Wc, Wo, masks, Wa);
    xprep<<<8192, 256>>>(x);
    conv_hmma<<<2048, 256, CV_SMEM>>>(bc);
    mcau_hmma<<<2048, 256, MC_SMEM>>>(lms, bo, ba, out);
}

// round 17
// speedup vs baseline: 2.9348x; 1.0068x over previous
#include <cuda_runtime.h>
#include <cuda_fp16.h>

#define BB 4
#define CIN 64
#define CO 128
#define HH 256
#define WW 256
#define HWP 65536
#define NOUT (BB*4*HWP)   // 1048576

typedef unsigned long long u64;

// scratch
__device__ __align__(256) unsigned short g_xh[(size_t)BB * HWP * 64]; // x fp16, [b][pix][ci]
__device__ __align__(256) unsigned char  g_wp[9 * 16384];             // conv weights fp16, swizzled
__device__ __align__(256) unsigned char  g_hf[(size_t)BB * HWP * 256];// h fp16 pixel-major [b][pix][c]
__device__ __align__(256) unsigned char  g_wm[64 * 256];              // Wm fp16, 256B-row swizzled
__device__ __align__(256) unsigned char  g_wau[9 * 16 * 256];         // Wau fp16 (rows 4-15 zero), swizzled

// ---- fast transcendentals --------------------------------------------------
__device__ __forceinline__ float fast_ex2(float x) {
    float e; asm("ex2.approx.f32 %0, %1;" : "=f"(e) : "f"(x)); return e;
}
__device__ __forceinline__ float fast_rcp(float x) {
    float r; asm("rcp.approx.f32 %0, %1;" : "=f"(r) : "f"(x)); return r;
}
__device__ __forceinline__ float fast_sigmoid(float x) {
    return fast_rcp(1.0f + fast_ex2(-x * 1.4426950408889634f));
}

// ---- cp.async helpers -----------------------------------------------------
__device__ __forceinline__ void cpa16(unsigned saddr, const void* gaddr) {
    asm volatile("cp.async.cg.shared.global [%0], [%1], 16;"
                 :: "r"(saddr), "l"(gaddr));
}
__device__ __forceinline__ void cpa16z(unsigned saddr, const void* gaddr, int ok) {
    asm volatile("cp.async.cg.shared.global [%0], [%1], 16, %2;"
                 :: "r"(saddr), "l"(gaddr), "r"(ok ? 16 : 0));
}
__device__ __forceinline__ void cpa_commit() {
    asm volatile("cp.async.commit_group;");
}
__device__ __forceinline__ void cpa_wait_all() {
    asm volatile("cp.async.wait_group 0;");
}

// ---- legacy tensor core ---------------------------------------------------
__device__ __forceinline__ void ldmx4(unsigned& r0, unsigned& r1,
                                      unsigned& r2, unsigned& r3, unsigned a) {
    asm volatile("ldmatrix.sync.aligned.m8n8.x4.shared.b16 {%0,%1,%2,%3}, [%4];"
                 : "=r"(r0), "=r"(r1), "=r"(r2), "=r"(r3) : "r"(a));
}
__device__ __forceinline__ void mma_f16(float* d, unsigned a0, unsigned a1,
                                        unsigned a2, unsigned a3,
                                        unsigned b0, unsigned b1) {
    asm volatile(
        "mma.sync.aligned.m16n8k16.row.col.f32.f16.f16.f32 "
        "{%0,%1,%2,%3}, {%4,%5,%6,%7}, {%8,%9}, {%0,%1,%2,%3};"
        : "+f"(d[0]), "+f"(d[1]), "+f"(d[2]), "+f"(d[3])
        : "r"(a0), "r"(a1), "r"(a2), "r"(a3), "r"(b0), "r"(b1));
}
__device__ __forceinline__ int swz(int off)    { return off ^ ((off >> 3) & 0x70); }
__device__ __forceinline__ int swz256(int off) { return off ^ (((off >> 8) & 7) << 4); }

// ---------------------------------------------------------------------------
// Prep A (fused): conv weights + Wm + Wau -> fp16 swizzled tiles. grid 392.
// ---------------------------------------------------------------------------
__global__ void allwprep(const float* __restrict__ Wc, const float* __restrict__ Wo,
                         const float* __restrict__ masks, const float* __restrict__ Wa) {
    const int blk = blockIdx.x, tid = threadIdx.x;
    if (blk < 288) {                       // conv weights: 73728 elems
        int i = blk * 256 + tid;
        int tap = i >> 13, rem = i & 8191, cout = rem >> 6, ci = rem & 63;
        __half h = __float2half_rn(Wc[cout * 576 + ci * 9 + tap]);
        *(unsigned short*)(g_wp + tap * 16384 + swz(cout * 128 + ci * 2)) =
            *reinterpret_cast<unsigned short*>(&h);
    } else if (blk < 320) {                // Wm: 8192 elems
        int i = (blk - 288) * 256 + tid;
        int r = i >> 7, c = i & 127, t = r >> 2, o = r & 3;
        __half h = __float2half_rn(Wo[o * 128 + c] * masks[t * 128 + c]);
        *(unsigned short*)(g_wm + r * 256 + ((c * 2) ^ ((r & 7) << 4))) =
            *reinterpret_cast<unsigned short*>(&h);
    } else {                               // Wau: 18432 elems
        int i = (blk - 320) * 256 + tid;
        int tap = i >> 11, rem = i & 2047, r = rem >> 7, c = rem & 127;
        float v = (r < 4) ? Wa[(r * 128 + c) * 9 + tap] : 0.f;
        __half h = __float2half_rn(v);
        *(unsigned short*)(g_wau + tap * 4096 + r * 256 + ((c * 2) ^ ((r & 7) << 4))) =
            *reinterpret_cast<unsigned short*>(&h);
    }
}

// ---------------------------------------------------------------------------
// Prep B: transpose x to pixel-major fp16: g_xh[b][pix][ci]
// ---------------------------------------------------------------------------
__global__ void xprep(const float* __restrict__ x) {
    __shared__ unsigned short shh[32 * 66];
    const int bx = blockIdx.x;
    const int b = bx >> 11;
    const int px0 = (bx & 2047) * 32;
    const int tid = threadIdx.x;
    for (int i = tid; i < 2048; i += 256) {
        int ci = i >> 5, p = i & 31;
        __half h = __float2half_rn(x[(((size_t)b * 64 + ci) << 16) + px0 + p]);
        shh[p * 66 + ci] = *reinterpret_cast<unsigned short*>(&h);
    }
    __syncthreads();
    for (int i = tid; i < 1024; i += 256) {
        int p = i >> 5, j = i & 31;
        unsigned vh = shh[p * 66 + 2 * j] | ((unsigned)shh[p * 66 + 2 * j + 1] << 16);
        reinterpret_cast<unsigned*>(g_xh)[((size_t)b * HWP + px0 + p) * 32 + j] = vh;
    }
}

// ---------------------------------------------------------------------------
// Kernel 1: conv1 via mma.sync fp16, epilogue writes g_hf directly.
// (unchanged from R15 — at the legacy-HMMA MAC floor)
// ---------------------------------------------------------------------------
#define SB_BYTES 49920
#define CV_SMEM (SB_BYTES + 32768 + 1024)
#define STG_PITCH 272     // 17*16: 16B-aligned rows, conflict-free STS.16 scatter

__global__ __launch_bounds__(256, 2) void conv_hmma(const float* __restrict__ bc) {
    extern __shared__ unsigned char dsm[];
    const int tid = threadIdx.x;
    const int w = tid >> 5, lane = tid & 31;
    const int blk = blockIdx.x;
    const int xh = blk & 1, y = (blk >> 1) & 255, b = blk >> 9;
    const int x0 = xh * 128;

    unsigned raw = (unsigned)__cvta_generic_to_shared(dsm);
    unsigned base = (raw + 1023) & ~1023u;
    unsigned char* smbase = dsm + (base - raw);
    unsigned sBh = base, sA = base + SB_BYTES;

    for (int i = tid; i < 3120; i += 256) {
        int r = i >> 3, c = i & 7;
        int ky = r / 130, p = r % 130;
        int gy = y + ky - 1, gx = x0 + p - 1;
        int ok = (gy >= 0 && gy < HH && gx >= 0 && gx < WW);
        const unsigned char* src = (const unsigned char*)g_xh
            + ((size_t)(b * HWP + (ok ? gy * WW + gx : 0)) * 128) + c * 16;
        cpa16z(sBh + swz(r * 128 + c * 16), src, ok);
    }
    cpa_commit();

    auto prefA = [&](int t, int buf) {
        const unsigned char* src = g_wp + t * 16384;
        unsigned dst = sA + buf * 16384;
#pragma unroll
        for (int j = 0; j < 4; j++) {
            int off = (tid * 4 + j) * 16;
            cpa16(dst + off, src + off);
        }
        cpa_commit();
    };
    prefA(0, 0);

    const int arow = (16 * w + (lane & 7) + ((lane >> 3) & 1) * 8) * 128
                   + ((lane >> 4) & 1) * 16;
    const int pxl  = (lane & 7) + ((lane >> 4) & 1) * 8;
    const int kextB = ((lane >> 3) & 1) * 16;

    float d[16][4];
#pragma unroll
    for (int j = 0; j < 16; j++)
#pragma unroll
        for (int q = 0; q < 4; q++) d[j][q] = 0.f;

    for (int t = 0; t < 9; t++) {
        cpa_wait_all();
        __syncthreads();
        if (t < 8) prefA(t + 1, (t + 1) & 1);

        const int rowb = (t / 3) * 130 + (t % 3);
        unsigned Abuf = sA + (t & 1) * 16384;
#pragma unroll
        for (int k = 0; k < 4; k++) {
            unsigned a0, a1, a2, a3;
            ldmx4(a0, a1, a2, a3, Abuf + swz(arow + k * 32));
            const int bc0 = (rowb + pxl) * 128 + k * 32 + kextB;
#pragma unroll
            for (int jp = 0; jp < 8; jp++) {
                unsigned b0, b1, b2, b3;
                ldmx4(b0, b1, b2, b3, sBh + swz(bc0 + jp * 2048));
                mma_f16(d[2 * jp],     a0, a1, a2, a3, b0, b1);
                mma_f16(d[2 * jp + 1], a0, a1, a2, a3, b2, b3);
            }
        }
        __syncthreads();
    }
    // after final barrier: sBh region free -> reuse as fp16 pixel-major staging

    const int g = lane >> 2, c2 = (lane & 3) * 2;
    const int cout0 = 16 * w + g;
    const float bias0 = bc[cout0], bias1 = bc[cout0 + 8];
#pragma unroll
    for (int j = 0; j < 16; j++) {
        int px = j * 8 + c2;
        __half v00 = __float2half_rn(d[j][0] + bias0);
        __half v01 = __float2half_rn(d[j][1] + bias0);
        __half v10 = __float2half_rn(d[j][2] + bias1);
        __half v11 = __float2half_rn(d[j][3] + bias1);
        *(__half*)(smbase + px * STG_PITCH + cout0 * 2)             = v00;
        *(__half*)(smbase + (px + 1) * STG_PITCH + cout0 * 2)       = v01;
        *(__half*)(smbase + px * STG_PITCH + (cout0 + 8) * 2)       = v10;
        *(__half*)(smbase + (px + 1) * STG_PITCH + (cout0 + 8) * 2) = v11;
    }
    __syncthreads();

    unsigned char* dstbase = g_hf + ((size_t)(b * HWP + y * WW + x0)) * 256;
#pragma unroll
    for (int jj = 0; jj < 8; jj++) {
        int i = jj * 256 + tid;          // < 2048
        int px = i >> 4, c16 = i & 15;
        uint4 v = *reinterpret_cast<const uint4*>(smbase + px * STG_PITCH + c16 * 16);
        *reinterpret_cast<uint4*>(dstbase + px * 256 + c16 * 16) = v;
    }
}

// ---------------------------------------------------------------------------
// Kernel 2: mc + au on HMMA. au accumulators split by k-parity (4 chains);
// divide-free h fill with GLOBAL-row swizzle (R16 bug fixed).
// ---------------------------------------------------------------------------
#define H_TILE 99840                 // 390 * 256
#define MC_SMEM (H_TILE + 16384 + 36864 + 1024)

__global__ __launch_bounds__(256, 1) void mcau_hmma(
    const float* __restrict__ lms, const float* __restrict__ bo,
    const float* __restrict__ ba, float* __restrict__ out)
{
    extern __shared__ unsigned char dsm2[];
    const int tid = threadIdx.x;
    const int w = tid >> 5, lane = tid & 31;
    const int blk = blockIdx.x;
    const int xh = blk & 1, y = (blk >> 1) & 255, b = blk >> 9;
    const int x0 = xh * 128;

    unsigned raw = (unsigned)__cvta_generic_to_shared(dsm2);
    unsigned base = (raw + 1023) & ~1023u;
    unsigned char* smbase = dsm2 + (base - raw);
    unsigned sH = base, sWm = base + H_TILE, sWau = sWm + 16384;

    // ---- h-tile fill: ky-outer, divide-free, swizzle on GLOBAL row offset --
#pragma unroll
    for (int ky = 0; ky < 3; ky++) {
        int gy = y + ky - 1;
        int okrow = (gy >= 0 && gy < HH);
        const unsigned char* rowsrc = g_hf
            + ((size_t)(b * HWP + (okrow ? gy * WW : 0))) * 256;
        const int rbase = ky * 130 * 256;            // global byte offset of row block
        for (int s = tid; s < 2080; s += 256) {      // 130 px x 16 chunks
            int p = s >> 4, c16 = s & 15;
            int gx = x0 + p - 1;
            int ok = okrow && (gx >= 0) && (gx < WW);
            const unsigned char* src = rowsrc + (size_t)(ok ? gx : 0) * 256 + c16 * 16;
            cpa16z(sH + swz256(rbase + p * 256 + c16 * 16), src, ok);
        }
    }
    for (int i = tid; i < 3328; i += 256) {          // Wm 1024 + Wau 2304 (16B units)
        if (i < 1024) cpa16(sWm + i * 16, g_wm + i * 16);
        else {
            int j = i - 1024;
            cpa16(sWau + j * 16, g_wau + j * 16);
        }
    }
    cpa_commit();
    cpa_wait_all();
    __syncthreads();

    const int n0 = w * 16;
    const int pxl  = (lane & 7) + ((lane >> 4) & 1) * 8;
    const int kextB = ((lane >> 3) & 1) * 16;
    const int arowl = ((lane & 7) + ((lane >> 3) & 1) * 8) * 256
                    + ((lane >> 4) & 1) * 16;

    float dmc[4][2][4];
    float dau[2][2][4];                              // [k-parity][nt][4]
#pragma unroll
    for (int m = 0; m < 4; m++)
#pragma unroll
        for (int nt = 0; nt < 2; nt++)
#pragma unroll
            for (int q = 0; q < 4; q++) dmc[m][nt][q] = 0.f;
#pragma unroll
    for (int kp = 0; kp < 2; kp++)
#pragma unroll
        for (int nt = 0; nt < 2; nt++)
#pragma unroll
            for (int q = 0; q < 4; q++) dau[kp][nt][q] = 0.f;

#pragma unroll
    for (int tap = 0; tap < 9; tap++) {
        const int rowb = (tap / 3) * 130 + (tap % 3);
#pragma unroll
        for (int k = 0; k < 8; k++) {
            unsigned b0, b1, b2, b3;
            ldmx4(b0, b1, b2, b3,
                  sH + swz256((rowb + n0 + pxl) * 256 + k * 32 + kextB));
            unsigned a0, a1, a2, a3;
            ldmx4(a0, a1, a2, a3, sWau + tap * 4096 + swz256(arowl + k * 32));
            mma_f16(dau[k & 1][0], a0, a1, a2, a3, b0, b1);
            mma_f16(dau[k & 1][1], a0, a1, a2, a3, b2, b3);
            if (tap == 4) {                          // center tap -> mc GEMM
#pragma unroll
                for (int m = 0; m < 4; m++) {
                    unsigned m0, m1, m2, m3;
                    ldmx4(m0, m1, m2, m3,
                          sWm + swz256(m * 4096 + arowl + k * 32));
                    mma_f16(dmc[m][0], m0, m1, m2, m3, b0, b1);
                    mma_f16(dmc[m][1], m0, m1, m2, m3, b2, b3);
                }
            }
        }
    }
    __syncthreads();   // everyone done reading sH

    // ---- store D to smem overlay: sD[px][68 floats] ----
    float* sD = reinterpret_cast<float*>(smbase);
    const int g = lane >> 2, c2 = (lane & 3) * 2;
#pragma unroll
    for (int m = 0; m < 4; m++)
#pragma unroll
        for (int nt = 0; nt < 2; nt++) {
            int pxb = n0 + nt * 8 + c2;
            int r = m * 16 + g;
            sD[pxb * 68 + r]           = dmc[m][nt][0];
            sD[(pxb + 1) * 68 + r]     = dmc[m][nt][1];
            sD[pxb * 68 + r + 8]       = dmc[m][nt][2];
            sD[(pxb + 1) * 68 + r + 8] = dmc[m][nt][3];
        }
    if (g < 4) {
#pragma unroll
        for (int nt = 0; nt < 2; nt++) {
            int pxb = n0 + nt * 8 + c2;
            sD[pxb * 68 + 64 + g]       = dau[0][nt][0] + dau[1][nt][0];
            sD[(pxb + 1) * 68 + 64 + g] = dau[0][nt][1] + dau[1][nt][1];
        }
    }
    __syncthreads();

    // ---- epilogue: 2 threads/px, t-split 8/8, batched-rcp tanh ----
    const int px = tid >> 1, half = tid & 1;
    const float* dp = sD + px * 68 + half * 32;
    float vals[32];
#pragma unroll
    for (int q = 0; q < 8; q++) {
        float4 v4 = reinterpret_cast<const float4*>(dp)[q];
        vals[4 * q] = v4.x; vals[4 * q + 1] = v4.y;
        vals[4 * q + 2] = v4.z; vals[4 * q + 3] = v4.w;
    }
    const float bov[4] = { bo[0], bo[1], bo[2], bo[3] };
    float sumS[4] = {0.f, 0.f, 0.f, 0.f}, sumQ[4] = {0.f, 0.f, 0.f, 0.f};
#pragma unroll
    for (int g4 = 0; g4 < 4; g4++) {
        float dd[8];
#pragma unroll
        for (int i = 0; i < 8; i++) {
            float v = vals[g4 * 8 + i] + bov[i & 3];
            float xc = fminf(v, 4.8f);
            dd[i] = 1.0f + fast_ex2(xc * 2.8853900817779268f);
        }
        float p01 = dd[0] * dd[1], p23 = dd[2] * dd[3];
        float p45 = dd[4] * dd[5], p67 = dd[6] * dd[7];
        float p0123 = p01 * p23, p4567 = p45 * p67;
        float r = fast_rcp(p0123 * p4567);
        float r0123 = r * p4567, r4567 = r * p0123;
        float i01 = r0123 * p23, i23 = r0123 * p01;
        float i45 = r4567 * p67, i67 = r4567 * p45;
        float inv[8];
        inv[0] = i01 * dd[1]; inv[1] = i01 * dd[0];
        inv[2] = i23 * dd[3]; inv[3] = i23 * dd[2];
        inv[4] = i45 * dd[5]; inv[5] = i45 * dd[4];
        inv[6] = i67 * dd[7]; inv[7] = i67 * dd[6];
#pragma unroll
        for (int i = 0; i < 8; i++) {
            float s = fmaf(-2.f, inv[i], 1.f);
            int o = i & 3;
            sumS[o] += s;
            sumQ[o] = fmaf(s, s, sumQ[o]);
        }
    }

    const int pix = y * WW + x0 + px;
#pragma unroll
    for (int o = 0; o < 4; o++) {
        float S = sumS[o] + __shfl_xor_sync(0xFFFFFFFFu, sumS[o], 1);
        float Q = sumQ[o] + __shfl_xor_sync(0xFFFFFFFFu, sumQ[o], 1);
        if ((o >> 1) == half) {
            float mn  = S * 0.0625f;
            float var = fmaxf((Q - 16.f * mn * mn) * (1.f / 15.f), 0.f);
            int oidx = (b * 4 + o) * HWP + pix;
            out[NOUT + oidx]     = var;              // EU
            out[2 * NOUT + oidx] = mn + lms[oidx];   // mean
        }
    }
    if (half == 0) {                                 // AU
#pragma unroll
        for (int o = 0; o < 4; o++) {
            float v = sD[px * 68 + 64 + o];
            out[(b * 4 + o) * HWP + pix] = fast_sigmoid(v + ba[o]);
        }
    }
}

// ---------------------------------------------------------------------------
extern "C" void kernel_launch(void* const* d_in, const int* in_sizes, int n_in,
                              void* d_out, int out_size) {
    const float* x     = (const float*)d_in[0];
    const float* lms   = (const float*)d_in[1];
    const float* Wc    = (const float*)d_in[2];
    const float* bc    = (const float*)d_in[3];
    const float* Wo    = (const float*)d_in[4];
    const float* bo    = (const float*)d_in[5];
    const float* Wa    = (const float*)d_in[6];
    const float* ba    = (const float*)d_in[7];
    const float* masks = (const float*)d_in[8];
    float* out = (float*)d_out;

    cudaFuncSetAttribute(conv_hmma,
                         cudaFuncAttributeMaxDynamicSharedMemorySize, CV_SMEM);
    cudaFuncSetAttribute(mcau_hmma,
                         cudaFuncAttributeMaxDynamicSharedMemorySize, MC_SMEM);

    allwprep<<<392, 256>>>(Wc, Wo, masks, Wa);
    xprep<<<8192, 256>>>(x);
    conv_hmma<<<2048, 256, CV_SMEM>>>(bc);
    mcau_hmma<<<2048, 256, MC_SMEM>>>(lms, bo, ba, out);
}